// round 1
// baseline (speedup 1.0000x reference)
#include <cuda_runtime.h>
#include <math.h>

// ---- problem dims ----
#define Bb   16
#define Ll   512
#define Mm   32
#define PREDp 96
#define Pp   16
#define Sss  8
#define Dd   128
#define NSTn 16
#define DCc  4
#define NLl  4
#define Nn   63
#define DIi  256
#define DTRr 8
#define BMr  512          // B*M rows (and B*M sequences for token mamba)
#define TT   32256        // total tokens per activation buffer (= 512*63 = 1008*32)
#define BNb  1008         // B*N sequences for channel mamba

// ---- static device scratch (no allocations allowed) ----
__device__ float g_y[9][(size_t)TT * Dd];   // slot0 = h (yT[0]==yC[0]); 1..4 = yT[1..4]; 5..8 = yC[1..4]
__device__ float g_xn[(size_t)BMr * Ll];
__device__ float g_mean[BMr];
__device__ float g_std[BMr];
__device__ float g_tokin[(size_t)TT * Dd];
__device__ float g_norm[(size_t)TT * Dd];
__device__ float g_chr[(size_t)TT * Dd];
__device__ float g_chout[(size_t)TT * Dd];
__device__ float g_xz[(size_t)TT * 2 * DIi];
__device__ float g_u[(size_t)TT * DIi];
__device__ float g_dtv[(size_t)TT * DIi];
__device__ float g_xdbl[(size_t)TT * 40];
__device__ float g_ys[(size_t)TT * DIi];
__device__ float g_tmp[(size_t)TT * Dd];
__device__ float g_head[(size_t)BMr * PREDp];

// ======================= kernels =======================

// per-(b,m): mean / unbiased std over L, write normalized transposed series (BM, L)
__global__ void k_stats(const float* __restrict__ x, float* __restrict__ mean,
                        float* __restrict__ stdv, float* __restrict__ xn) {
    int bm = blockIdx.x;
    int b = bm >> 5, m = bm & 31;
    int tid = threadIdx.x;
    float s = 0.f, sq = 0.f;
    for (int l = tid; l < Ll; l += 256) {
        float v = x[((size_t)b * Ll + l) * Mm + m];
        s += v; sq += v * v;
    }
    __shared__ float sh1[256], sh2[256];
    sh1[tid] = s; sh2[tid] = sq;
    __syncthreads();
    for (int o = 128; o; o >>= 1) {
        if (tid < o) { sh1[tid] += sh1[tid + o]; sh2[tid] += sh2[tid + o]; }
        __syncthreads();
    }
    __shared__ float smu, ssd;
    if (tid == 0) {
        float mu = sh1[0] / (float)Ll;
        float var = (sh2[0] - (float)Ll * mu * mu) / (float)(Ll - 1);
        if (var < 0.f) var = 0.f;
        float sd = sqrtf(var) + 1e-5f;
        smu = mu; ssd = sd;
        mean[bm] = mu; stdv[bm] = sd;
    }
    __syncthreads();
    float inv = 1.f / ssd;
    float mu = smu;
    for (int l = tid; l < Ll; l += 256) {
        xn[(size_t)bm * Ll + l] = (x[((size_t)b * Ll + l) * Mm + m] - mu) * inv;
    }
}

// patch embed: h[bm,n,d] = sum_p xn[bm, n*S+p]*pw[d,p] + pb[d] + pos[n,d]
__global__ void k_patch(const float* __restrict__ xn, const float* __restrict__ pw,
                        const float* __restrict__ pb, const float* __restrict__ pos,
                        float* __restrict__ h) {
    int blk = blockIdx.x;             // bm*Nn + n
    int n = blk % Nn, bm = blk / Nn;
    int d = threadIdx.x;
    __shared__ float xs[Pp];
    if (d < Pp) xs[d] = xn[(size_t)bm * Ll + n * Sss + d];
    __syncthreads();
    float acc = pb[d];
#pragma unroll
    for (int p = 0; p < Pp; ++p) acc = fmaf(xs[p], pw[d * Pp + p], acc);
    acc += pos[n * Dd + d];
    h[(size_t)blk * Dd + d] = acc;
}

struct P5 { const float* p[5]; };

// out = sum softmax(ra[0..na))[j]*pa[j] + sum softmax(rb[0..nb))[j]*pb[j]
__global__ void k_combine(float* __restrict__ out, P5 pa, int na, const float* __restrict__ ra,
                          P5 pb, int nb, const float* __restrict__ rb, size_t n) {
    __shared__ float ca[5], cb[5];
    if (threadIdx.x == 0) {
        float mx = -1e30f;
        for (int i = 0; i < na; ++i) mx = fmaxf(mx, ra[i]);
        float s = 0.f;
        for (int i = 0; i < na; ++i) { ca[i] = __expf(ra[i] - mx); s += ca[i]; }
        for (int i = 0; i < na; ++i) ca[i] /= s;
        mx = -1e30f;
        for (int i = 0; i < nb; ++i) mx = fmaxf(mx, rb[i]);
        s = 0.f;
        for (int i = 0; i < nb; ++i) { cb[i] = __expf(rb[i] - mx); s += cb[i]; }
        for (int i = 0; i < nb; ++i) cb[i] /= s;
    }
    __syncthreads();
    for (size_t i = (size_t)blockIdx.x * blockDim.x + threadIdx.x; i < n;
         i += (size_t)gridDim.x * blockDim.x) {
        float acc = 0.f;
        for (int j = 0; j < na; ++j) acc = fmaf(ca[j], pa.p[j][i], acc);
        for (int j = 0; j < nb; ++j) acc = fmaf(cb[j], pb.p[j][i], acc);
        out[i] = acc;
    }
}

// layernorm over D=128, one warp per row (4 rows / 128-thread block)
__global__ void k_ln(const float* __restrict__ x, const float* __restrict__ w,
                     const float* __restrict__ bia, float* __restrict__ out, int rows) {
    int warp = threadIdx.x >> 5, lane = threadIdx.x & 31;
    int row = blockIdx.x * 4 + warp;
    if (row >= rows) return;
    const float* xr = x + (size_t)row * Dd;
    float v0 = xr[lane], v1 = xr[lane + 32], v2 = xr[lane + 64], v3 = xr[lane + 96];
    float s = v0 + v1 + v2 + v3;
#pragma unroll
    for (int o = 16; o; o >>= 1) s += __shfl_xor_sync(0xffffffffu, s, o);
    float mu = s * (1.f / Dd);
    float d0 = v0 - mu, d1 = v1 - mu, d2 = v2 - mu, d3 = v3 - mu;
    float q = d0 * d0 + d1 * d1 + d2 * d2 + d3 * d3;
#pragma unroll
    for (int o = 16; o; o >>= 1) q += __shfl_xor_sync(0xffffffffu, q, o);
    float r = rsqrtf(q * (1.f / Dd) + 1e-5f);
    float* orow = out + (size_t)row * Dd;
    orow[lane]      = d0 * r * w[lane]      + bia[lane];
    orow[lane + 32] = d1 * r * w[lane + 32] + bia[lane + 32];
    orow[lane + 64] = d2 * r * w[lane + 64] + bia[lane + 64];
    orow[lane + 96] = d3 * r * w[lane + 96] + bia[lane + 96];
}

// LN over D fused with (B,M,N,D)->(B,N,M,D) transpose: read chin (BM,N,D), write chr (B*N,M,D)
__global__ void k_lnT(const float* __restrict__ x, const float* __restrict__ w,
                      const float* __restrict__ bia, float* __restrict__ out) {
    int warp = threadIdx.x >> 5, lane = threadIdx.x & 31;
    int orow = blockIdx.x * 4 + warp;      // (b*Nn+n)*Mm + m
    if (orow >= TT) return;
    int m = orow & 31;
    int bn = orow >> 5;
    int n = bn % Nn, b = bn / Nn;
    int irow = (b * Mm + m) * Nn + n;
    const float* xr = x + (size_t)irow * Dd;
    float v0 = xr[lane], v1 = xr[lane + 32], v2 = xr[lane + 64], v3 = xr[lane + 96];
    float s = v0 + v1 + v2 + v3;
#pragma unroll
    for (int o = 16; o; o >>= 1) s += __shfl_xor_sync(0xffffffffu, s, o);
    float mu = s * (1.f / Dd);
    float d0 = v0 - mu, d1 = v1 - mu, d2 = v2 - mu, d3 = v3 - mu;
    float q = d0 * d0 + d1 * d1 + d2 * d2 + d3 * d3;
#pragma unroll
    for (int o = 16; o; o >>= 1) q += __shfl_xor_sync(0xffffffffu, q, o);
    float r = rsqrtf(q * (1.f / Dd) + 1e-5f);
    float* orow_p = out + (size_t)orow * Dd;
    orow_p[lane]      = d0 * r * w[lane]      + bia[lane];
    orow_p[lane + 32] = d1 * r * w[lane + 32] + bia[lane + 32];
    orow_p[lane + 64] = d2 * r * w[lane + 64] + bia[lane + 64];
    orow_p[lane + 96] = d3 * r * w[lane + 96] + bia[lane + 96];
}

// yC_next[(b,m,n,d)] = chout[(b,n,m,d)] + chin[(b,m,n,d)]
__global__ void k_transback(const float* __restrict__ chout, const float* __restrict__ chin,
                            float* __restrict__ out) {
    size_t total = (size_t)TT * Dd;
    for (size_t i = (size_t)blockIdx.x * blockDim.x + threadIdx.x; i < total;
         i += (size_t)gridDim.x * blockDim.x) {
        int d = (int)(i & 127);
        size_t rest = i >> 7;
        int n = (int)(rest % Nn);
        int bm = (int)(rest / Nn);
        int m = bm & 31, b = bm >> 5;
        size_t src = (((size_t)(b * Nn + n) * Mm + m) << 7) + d;
        out[i] = chout[src] + chin[i];
    }
}

// depthwise causal (or reversed anticausal) conv + SiLU: xi = xz[:, 0:256]
__global__ void k_conv(const float* __restrict__ xz, const float* __restrict__ cw,
                       const float* __restrict__ cb, float* __restrict__ u,
                       int batch, int slen, int rev) {
    int idx = blockIdx.x * 256 + threadIdx.x;
    int total = batch * slen * DIi;
    if (idx >= total) return;
    int c = idx & 255;
    int row = idx >> 8;
    int s = row % slen, b = row / slen;
    float acc = cb[c];
#pragma unroll
    for (int k = 0; k < DCc; ++k) {
        int t = rev ? (s + 3 - k) : (s + k - 3);
        if (t >= 0 && t < slen)
            acc = fmaf(cw[c * DCc + k], xz[((size_t)(b * slen + t)) * (2 * DIi) + c], acc);
    }
    float sg = 1.f / (1.f + __expf(-acc));
    u[(size_t)row * DIi + c] = acc * sg;
}

// dt = softplus(xdbl[:, :8] @ dtw^T + dtb)
__global__ void k_dt(const float* __restrict__ xdbl, const float* __restrict__ dtw,
                     const float* __restrict__ dtb, float* __restrict__ dt, int rows) {
    int idx = blockIdx.x * 256 + threadIdx.x;
    if (idx >= rows * DIi) return;
    int c = idx & 255;
    int row = idx >> 8;
    const float* xr = xdbl + (size_t)row * 40;
    float acc = dtb[c];
#pragma unroll
    for (int r = 0; r < DTRr; ++r) acc = fmaf(xr[r], dtw[c * DTRr + r], acc);
    float sp = (acc > 20.f) ? acc : log1pf(__expf(acc));
    dt[idx] = sp;
}

// selective scan: one block per sequence (256 threads = DI channels), h[16] in registers.
// Fuses +u*D and *silu(z). rev=1 runs the time loop backwards (flip-scan-flip).
__global__ void k_scan(const float* __restrict__ dt, const float* __restrict__ u,
                       const float* __restrict__ xdbl, const float* __restrict__ xz,
                       const float* __restrict__ alog, const float* __restrict__ dssm,
                       float* __restrict__ y, int slen, int rev) {
    int b = blockIdx.x;
    int d = threadIdx.x;
    __shared__ float sBC[32];
    float a[NSTn];
#pragma unroll
    for (int n = 0; n < NSTn; ++n) a[n] = -__expf(alog[d * NSTn + n]);
    float a0 = a[0];
    bool geom = true;
#pragma unroll
    for (int n = 1; n < NSTn; ++n)
        geom = geom && (fabsf(a[n] - (float)(n + 1) * a0) <= 1e-4f * fabsf(a[n]));
    float dss = dssm[d];
    float h[NSTn];
#pragma unroll
    for (int n = 0; n < NSTn; ++n) h[n] = 0.f;

    for (int step = 0; step < slen; ++step) {
        int s = rev ? (slen - 1 - step) : step;
        size_t row = (size_t)b * slen + s;
        __syncthreads();
        if (d < 32) sBC[d] = xdbl[row * 40 + 8 + d];
        __syncthreads();
        float dtv = dt[row * DIi + d];
        float uv  = u[row * DIi + d];
        float du  = dtv * uv;
        float ysum = 0.f;
        if (geom) {
            float w = __expf(dtv * a0);
            float e = 1.f;
#pragma unroll
            for (int n = 0; n < NSTn; ++n) {
                e *= w;
                h[n] = fmaf(h[n], e, du * sBC[n]);
                ysum = fmaf(h[n], sBC[16 + n], ysum);
            }
        } else {
#pragma unroll
            for (int n = 0; n < NSTn; ++n) {
                float e = __expf(dtv * a[n]);
                h[n] = fmaf(h[n], e, du * sBC[n]);
                ysum = fmaf(h[n], sBC[16 + n], ysum);
            }
        }
        float zv = xz[row * (2 * DIi) + DIi + d];
        float sg = 1.f / (1.f + __expf(-zv));
        y[row * DIi + d] = (ysum + uv * dss) * (zv * sg);
    }
}

// Norm2D second LN: per (bm,d), LN over N with per-n weight/bias
__global__ void k_ln_n(const float* __restrict__ x, const float* __restrict__ w2,
                       const float* __restrict__ b2, float* __restrict__ out) {
    int idx = blockIdx.x * 256 + threadIdx.x;
    if (idx >= BMr * Dd) return;
    int d = idx & 127, bm = idx >> 7;
    const float* base = x + (size_t)bm * Nn * Dd + d;
    float s = 0.f, q = 0.f;
    for (int n = 0; n < Nn; ++n) { float v = base[(size_t)n * Dd]; s += v; q += v * v; }
    float mu = s * (1.f / Nn);
    float var = q * (1.f / Nn) - mu * mu;
    if (var < 0.f) var = 0.f;
    float r = rsqrtf(var + 1e-5f);
    float* ob = out + (size_t)bm * Nn * Dd + d;
    for (int n = 0; n < Nn; ++n)
        ob[(size_t)n * Dd] = (base[(size_t)n * Dd] - mu) * r * w2[n] + b2[n];
}

// final: out[b,p,m] = (head[bm,p] + hb[p]) * std[bm] + mean[bm]
__global__ void k_headep(const float* __restrict__ hv, const float* __restrict__ hb,
                         const float* __restrict__ mean, const float* __restrict__ stdv,
                         float* __restrict__ out) {
    int idx = blockIdx.x * 256 + threadIdx.x;
    if (idx >= Bb * PREDp * Mm) return;
    int m = idx % Mm;
    int p = (idx / Mm) % PREDp;
    int b = idx / (Mm * PREDp);
    int bm = b * Mm + m;
    out[idx] = (hv[(size_t)bm * PREDp + p] + hb[p]) * stdv[bm] + mean[bm];
}

// tiled SGEMM: C[M,N] = A[M,K] @ B[N,K]^T   (flags: 1 = accumulate into C, 2 = add R)
// K must be a multiple of 16 and 16B-aligned rows (all our K: 128, 256, 8064).
__global__ void k_sgemm(const float* __restrict__ A, const float* __restrict__ Bw,
                        float* __restrict__ C, const float* __restrict__ R,
                        int M, int N, int K, int flags) {
    __shared__ float As[16][64];
    __shared__ float Bs[16][64];
    int tid = threadIdx.x;                  // 256 threads
    int tx = tid & 15, ty = tid >> 4;
    int row0 = blockIdx.y * 64;
    int col0 = blockIdx.x * 64;
    float acc[4][4];
#pragma unroll
    for (int i = 0; i < 4; ++i)
#pragma unroll
        for (int j = 0; j < 4; ++j) acc[i][j] = 0.f;
    int lr = tid >> 2;
    int lc = (tid & 3) << 2;
    for (int k0 = 0; k0 < K; k0 += 16) {
        float4 va = make_float4(0.f, 0.f, 0.f, 0.f);
        int gr = row0 + lr;
        if (gr < M) va = *reinterpret_cast<const float4*>(A + (size_t)gr * K + k0 + lc);
        As[lc + 0][lr] = va.x; As[lc + 1][lr] = va.y; As[lc + 2][lr] = va.z; As[lc + 3][lr] = va.w;
        float4 vb = make_float4(0.f, 0.f, 0.f, 0.f);
        int gn = col0 + lr;
        if (gn < N) vb = *reinterpret_cast<const float4*>(Bw + (size_t)gn * K + k0 + lc);
        Bs[lc + 0][lr] = vb.x; Bs[lc + 1][lr] = vb.y; Bs[lc + 2][lr] = vb.z; Bs[lc + 3][lr] = vb.w;
        __syncthreads();
#pragma unroll
        for (int k = 0; k < 16; ++k) {
            float4 af = *reinterpret_cast<const float4*>(&As[k][ty << 2]);
            float4 bf = *reinterpret_cast<const float4*>(&Bs[k][tx << 2]);
            float aa[4] = {af.x, af.y, af.z, af.w};
            float bb[4] = {bf.x, bf.y, bf.z, bf.w};
#pragma unroll
            for (int i = 0; i < 4; ++i)
#pragma unroll
                for (int j = 0; j < 4; ++j)
                    acc[i][j] = fmaf(aa[i], bb[j], acc[i][j]);
        }
        __syncthreads();
    }
#pragma unroll
    for (int i = 0; i < 4; ++i) {
        int gr = row0 + (ty << 2) + i;
        if (gr >= M) continue;
#pragma unroll
        for (int j = 0; j < 4; ++j) {
            int gn = col0 + (tx << 2) + j;
            if (gn >= N) continue;
            size_t o = (size_t)gr * N + gn;
            float v = acc[i][j];
            if (flags & 2) v += R[o];
            if (flags & 1) v += C[o];
            C[o] = v;
        }
    }
}

// ======================= host orchestration =======================

extern "C" void kernel_launch(void* const* d_in, const int* in_sizes, int n_in,
                              void* d_out, int out_size) {
    (void)in_sizes; (void)n_in; (void)out_size;
    const float* x      = (const float*)d_in[0];
    const float* patchw = (const float*)d_in[1];
    const float* patchb = (const float*)d_in[2];
    const float* pos    = (const float*)d_in[3];
    const float* alpha  = (const float*)d_in[4];
    const float* beta   = (const float*)d_in[5];
    const float* theta  = (const float*)d_in[6];
    const float* gma    = (const float*)d_in[7];
    const float* tnw    = (const float*)d_in[8];
    const float* tnb    = (const float*)d_in[9];
    const float* cnw    = (const float*)d_in[10];
    const float* cnb    = (const float*)d_in[11];
    const float* inw    = (const float*)d_in[12];
    const float* cvw    = (const float*)d_in[13];
    const float* cvb    = (const float*)d_in[14];
    const float* xpw    = (const float*)d_in[15];
    const float* dtw    = (const float*)d_in[16];
    const float* dtbv   = (const float*)d_in[17];
    const float* alog   = (const float*)d_in[18];
    const float* dssm   = (const float*)d_in[19];
    const float* outw   = (const float*)d_in[20];
    const float* n2w1   = (const float*)d_in[21];
    const float* n2b1   = (const float*)d_in[22];
    const float* n2w2   = (const float*)d_in[23];
    const float* n2b2   = (const float*)d_in[24];
    const float* headw  = (const float*)d_in[25];
    const float* headb  = (const float*)d_in[26];

    float *p_y, *p_xn, *p_mean, *p_std, *p_tokin, *p_norm, *p_chr, *p_chout;
    float *p_xz, *p_u, *p_dt, *p_xdbl, *p_ys, *p_tmp, *p_head;
    cudaGetSymbolAddress((void**)&p_y,     g_y);
    cudaGetSymbolAddress((void**)&p_xn,    g_xn);
    cudaGetSymbolAddress((void**)&p_mean,  g_mean);
    cudaGetSymbolAddress((void**)&p_std,   g_std);
    cudaGetSymbolAddress((void**)&p_tokin, g_tokin);
    cudaGetSymbolAddress((void**)&p_norm,  g_norm);
    cudaGetSymbolAddress((void**)&p_chr,   g_chr);
    cudaGetSymbolAddress((void**)&p_chout, g_chout);
    cudaGetSymbolAddress((void**)&p_xz,    g_xz);
    cudaGetSymbolAddress((void**)&p_u,     g_u);
    cudaGetSymbolAddress((void**)&p_dt,    g_dtv);
    cudaGetSymbolAddress((void**)&p_xdbl,  g_xdbl);
    cudaGetSymbolAddress((void**)&p_ys,    g_ys);
    cudaGetSymbolAddress((void**)&p_tmp,   g_tmp);
    cudaGetSymbolAddress((void**)&p_head,  g_head);

    float* yT[5]; float* yC[5];
    yT[0] = p_y; yC[0] = p_y;
    for (int i = 1; i <= 4; ++i) {
        yT[i] = p_y + (size_t)i * TT * Dd;
        yC[i] = p_y + (size_t)(4 + i) * TT * Dd;
    }

    k_stats<<<BMr, 256>>>(x, p_mean, p_std, p_xn);
    k_patch<<<TT, Dd>>>(p_xn, patchw, patchb, pos, p_y);

    const size_t NE = (size_t)TT * Dd;
    const int cgrid = 4096;

    auto mamba = [&](const float* inp, int batch, int slen, int l, int r,
                     const float* resid, float* outp, int flags, int rev) {
        int rows = batch * slen;           // always 32256
        size_t lr = (size_t)(l * 3 + r);
        dim3 g1((2 * DIi + 63) / 64, (rows + 63) / 64);
        k_sgemm<<<g1, 256>>>(inp, inw + lr * 2 * DIi * Dd, p_xz, nullptr, rows, 2 * DIi, Dd, 0);
        k_conv<<<(rows * DIi + 255) / 256, 256>>>(p_xz, cvw + lr * DIi * DCc, cvb + lr * DIi,
                                                  p_u, batch, slen, rev);
        dim3 g2(1, (rows + 63) / 64);
        k_sgemm<<<g2, 256>>>(p_u, xpw + lr * 40 * DIi, p_xdbl, nullptr, rows, 40, DIi, 0);
        k_dt<<<(rows * DIi + 255) / 256, 256>>>(p_xdbl, dtw + lr * DIi * DTRr, dtbv + lr * DIi,
                                                p_dt, rows);
        k_scan<<<batch, DIi>>>(p_dt, p_u, p_xdbl, p_xz, alog + lr * DIi * NSTn, dssm + lr * DIi,
                               p_ys, slen, rev);
        dim3 g3((Dd + 63) / 64, (rows + 63) / 64);
        k_sgemm<<<g3, 256>>>(p_ys, outw + lr * Dd * DIi, outp, resid, rows, Dd, DIi, flags);
    };

    for (int l = 0; l < NLl; ++l) {
        // ---- token mixing ----
        P5 pa = {}, pb = {};
        for (int i = 0; i <= l; ++i) { pa.p[i] = yT[i]; pb.p[i] = yC[i]; }
        k_combine<<<cgrid, 256>>>(p_tokin, pa, l + 1, alpha + l * NLl,
                                  pb, l + 1, beta + l * NLl, NE);
        k_ln<<<TT / 4, 128>>>(p_tokin, tnw + l * Dd, tnb + l * Dd, p_norm, TT);
        mamba(p_norm, BMr, Nn, l, 0, p_tokin, yT[l + 1], /*flags=resid*/2, /*rev*/0);

        // ---- channel mixing (bidirectional) ----
        P5 pc = {}, pd = {};
        for (int i = 0; i <= l + 1; ++i) pc.p[i] = yT[i];
        for (int i = 0; i <= l; ++i)     pd.p[i] = yC[i];
        k_combine<<<cgrid, 256>>>(p_tokin, pc, l + 2, theta + l * (NLl + 1),
                                  pd, l + 1, gma + l * NLl, NE);
        k_lnT<<<TT / 4, 128>>>(p_tokin, cnw + l * Dd, cnb + l * Dd, p_chr);
        mamba(p_chr, BNb, Mm, l, 1, nullptr, p_chout, /*write*/0, /*rev*/0);
        mamba(p_chr, BNb, Mm, l, 2, nullptr, p_chout, /*accum*/1, /*rev*/1);
        k_transback<<<cgrid, 256>>>(p_chout, p_tokin, yC[l + 1]);
    }

    // ---- Norm2D + head ----
    k_ln<<<TT / 4, 128>>>(yC[4], n2w1, n2b1, p_tmp, TT);
    k_ln_n<<<(BMr * Dd + 255) / 256, 256>>>(p_tmp, n2w2, n2b2, p_norm);
    dim3 gh((PREDp + 63) / 64, (BMr + 63) / 64);
    k_sgemm<<<gh, 256>>>(p_norm, headw, p_head, nullptr, BMr, PREDp, Nn * Dd, 0);
    k_headep<<<(Bb * PREDp * Mm + 255) / 256, 256>>>(p_head, headb, p_mean, p_std,
                                                     (float*)d_out);
}

// round 3
// speedup vs baseline: 1.5500x; 1.5500x over previous
#include <cuda_runtime.h>
#include <cuda_bf16.h>
#include <math.h>
#include <stdint.h>

// ---- problem dims ----
#define Bb   16
#define Ll   512
#define Mm   32
#define PREDp 96
#define Pp   16
#define Sss  8
#define Dd   128
#define NSTn 16
#define DCc  4
#define NLl  4
#define Nn   63
#define DIi  256
#define DTRr 8
#define BMr  512
#define TT   32256        // = 512*63 = 1008*32 = 252*128
#define BNb  1008

// ---- static device scratch ----
__device__ float g_y[9][(size_t)TT * Dd];
__device__ float g_xn[(size_t)BMr * Ll];
__device__ float g_mean[BMr];
__device__ float g_std[BMr];
__device__ float g_tokin[(size_t)TT * Dd];
__device__ float g_norm[(size_t)TT * Dd];
__device__ float g_chr[(size_t)TT * Dd];
__device__ float g_chout[(size_t)TT * Dd];
__device__ float g_xz[(size_t)TT * 2 * DIi];
__device__ float g_u[(size_t)TT * DIi];
__device__ float g_dtv[(size_t)TT * DIi];
__device__ float g_xdbl[(size_t)TT * 40];
__device__ float g_ys[(size_t)TT * DIi];
__device__ float g_tmp[(size_t)TT * Dd];
__device__ float g_head[(size_t)BMr * PREDp];

// ======================= warp-mma bf16-split GEMM =======================
// C[M,NT] = A[M,K] @ Bw[NT,K]^T, fp32 in/out, bf16 hi/lo split (3 HMMA terms).
// grid = (ceil(NT/64), M/128), block = 256 (8 warps of 32x32 tiles).
// flags: 1 = accumulate into C, 2 = add R. K % 32 == 0.

#define SASTR 40   // smem row stride (bf16 elems), padded for conflict-free frags

__device__ __forceinline__ void mma16816(float* d, const uint32_t* a, const uint32_t* b) {
    asm volatile(
        "mma.sync.aligned.m16n8k16.row.col.f32.bf16.bf16.f32 "
        "{%0,%1,%2,%3},{%4,%5,%6,%7},{%8,%9},{%0,%1,%2,%3};"
        : "+f"(d[0]), "+f"(d[1]), "+f"(d[2]), "+f"(d[3])
        : "r"(a[0]), "r"(a[1]), "r"(a[2]), "r"(a[3]), "r"(b[0]), "r"(b[1]));
}

union BH2 { __nv_bfloat16 h[2]; uint32_t u; };

template <int NT>
__global__ __launch_bounds__(256) void k_mma(const float* __restrict__ A,
                                             const float* __restrict__ Bw,
                                             float* __restrict__ C,
                                             const float* __restrict__ R,
                                             int K, int flags) {
    __shared__ __nv_bfloat16 sA[2][128 * SASTR];
    __shared__ __nv_bfloat16 sB[2][64 * SASTR];

    int tid = threadIdx.x;
    int warp = tid >> 5, lane = tid & 31;
    int gq = lane >> 2, tig = lane & 3;          // group / thread-in-group
    int warpM = warp >> 1, warpN = warp & 1;
    int m0 = blockIdx.y * 128;
    int n0 = blockIdx.x * 64;

    float acc[2][4][4];
#pragma unroll
    for (int i = 0; i < 2; ++i)
#pragma unroll
        for (int j = 0; j < 4; ++j)
#pragma unroll
            for (int r = 0; r < 4; ++r) acc[i][j][r] = 0.f;

    float4 ra[4], rb[2];

    auto ldA = [&](int k0) {
#pragma unroll
        for (int t = 0; t < 4; ++t) {
            int gg = tid + t * 256;
            int row = gg >> 3, c = (gg & 7) << 2;
            ra[t] = *reinterpret_cast<const float4*>(A + (size_t)(m0 + row) * K + k0 + c);
        }
    };
    auto ldB = [&](int k0) {
#pragma unroll
        for (int t = 0; t < 2; ++t) {
            int gg = tid + t * 256;
            int row = gg >> 3, c = (gg & 7) << 2;
            int grow = n0 + row;
            if ((NT & 63) == 0 || grow < NT)
                rb[t] = *reinterpret_cast<const float4*>(Bw + (size_t)grow * K + k0 + c);
            else
                rb[t] = make_float4(0.f, 0.f, 0.f, 0.f);
        }
    };

    ldA(0); ldB(0);
    int nch = K >> 5;
    for (int ch = 0; ch < nch; ++ch) {
        // split + store staged registers to smem
#pragma unroll
        for (int t = 0; t < 4; ++t) {
            int gg = tid + t * 256;
            int row = gg >> 3, c = (gg & 7) << 2;
            float v[4] = {ra[t].x, ra[t].y, ra[t].z, ra[t].w};
            BH2 h0, h1, l0, l1;
#pragma unroll
            for (int q = 0; q < 2; ++q) {
                h0.h[q] = __float2bfloat16(v[q]);
                l0.h[q] = __float2bfloat16(v[q] - __bfloat162float(h0.h[q]));
                h1.h[q] = __float2bfloat16(v[2 + q]);
                l1.h[q] = __float2bfloat16(v[2 + q] - __bfloat162float(h1.h[q]));
            }
            uint32_t* ph = reinterpret_cast<uint32_t*>(&sA[0][row * SASTR + c]);
            uint32_t* pl = reinterpret_cast<uint32_t*>(&sA[1][row * SASTR + c]);
            ph[0] = h0.u; ph[1] = h1.u; pl[0] = l0.u; pl[1] = l1.u;
        }
#pragma unroll
        for (int t = 0; t < 2; ++t) {
            int gg = tid + t * 256;
            int row = gg >> 3, c = (gg & 7) << 2;
            float v[4] = {rb[t].x, rb[t].y, rb[t].z, rb[t].w};
            BH2 h0, h1, l0, l1;
#pragma unroll
            for (int q = 0; q < 2; ++q) {
                h0.h[q] = __float2bfloat16(v[q]);
                l0.h[q] = __float2bfloat16(v[q] - __bfloat162float(h0.h[q]));
                h1.h[q] = __float2bfloat16(v[2 + q]);
                l1.h[q] = __float2bfloat16(v[2 + q] - __bfloat162float(h1.h[q]));
            }
            uint32_t* ph = reinterpret_cast<uint32_t*>(&sB[0][row * SASTR + c]);
            uint32_t* pl = reinterpret_cast<uint32_t*>(&sB[1][row * SASTR + c]);
            ph[0] = h0.u; ph[1] = h1.u; pl[0] = l0.u; pl[1] = l1.u;
        }
        __syncthreads();
        if (ch + 1 < nch) { ldA((ch + 1) << 5); ldB((ch + 1) << 5); }

#pragma unroll
        for (int kk = 0; kk < 2; ++kk) {
            int kb = kk * 16 + 2 * tig;
            uint32_t ah[2][4], al[2][4];
#pragma unroll
            for (int i = 0; i < 2; ++i) {
                int r0 = warpM * 32 + i * 16 + gq;
                const uint32_t* p0h = reinterpret_cast<const uint32_t*>(&sA[0][r0 * SASTR + kb]);
                const uint32_t* p1h = reinterpret_cast<const uint32_t*>(&sA[0][(r0 + 8) * SASTR + kb]);
                const uint32_t* p0l = reinterpret_cast<const uint32_t*>(&sA[1][r0 * SASTR + kb]);
                const uint32_t* p1l = reinterpret_cast<const uint32_t*>(&sA[1][(r0 + 8) * SASTR + kb]);
                ah[i][0] = p0h[0]; ah[i][1] = p1h[0]; ah[i][2] = p0h[4]; ah[i][3] = p1h[4];
                al[i][0] = p0l[0]; al[i][1] = p1l[0]; al[i][2] = p0l[4]; al[i][3] = p1l[4];
            }
            uint32_t bh[4][2], bl[4][2];
#pragma unroll
            for (int j = 0; j < 4; ++j) {
                int n = warpN * 32 + j * 8 + gq;
                const uint32_t* pbh = reinterpret_cast<const uint32_t*>(&sB[0][n * SASTR + kb]);
                const uint32_t* pbl = reinterpret_cast<const uint32_t*>(&sB[1][n * SASTR + kb]);
                bh[j][0] = pbh[0]; bh[j][1] = pbh[4];
                bl[j][0] = pbl[0]; bl[j][1] = pbl[4];
            }
#pragma unroll
            for (int i = 0; i < 2; ++i)
#pragma unroll
                for (int j = 0; j < 4; ++j) {
                    mma16816(acc[i][j], ah[i], bh[j]);
                    mma16816(acc[i][j], ah[i], bl[j]);
                    mma16816(acc[i][j], al[i], bh[j]);
                }
        }
        __syncthreads();
    }

    // epilogue
#pragma unroll
    for (int i = 0; i < 2; ++i) {
        int grow = m0 + warpM * 32 + i * 16 + gq;
#pragma unroll
        for (int j = 0; j < 4; ++j) {
            int gcol = n0 + warpN * 32 + j * 8 + 2 * tig;
            if ((NT & 63) != 0 && gcol >= NT) continue;
            size_t o0 = (size_t)grow * NT + gcol;
            size_t o1 = (size_t)(grow + 8) * NT + gcol;
            float2 v0 = make_float2(acc[i][j][0], acc[i][j][1]);
            float2 v1 = make_float2(acc[i][j][2], acc[i][j][3]);
            if (flags & 2) {
                float2 t0 = *reinterpret_cast<const float2*>(R + o0);
                float2 t1 = *reinterpret_cast<const float2*>(R + o1);
                v0.x += t0.x; v0.y += t0.y; v1.x += t1.x; v1.y += t1.y;
            }
            if (flags & 1) {
                float2 t0 = *reinterpret_cast<const float2*>(C + o0);
                float2 t1 = *reinterpret_cast<const float2*>(C + o1);
                v0.x += t0.x; v0.y += t0.y; v1.x += t1.x; v1.y += t1.y;
            }
            *reinterpret_cast<float2*>(C + o0) = v0;
            *reinterpret_cast<float2*>(C + o1) = v1;
        }
    }
}

// ======================= supporting kernels =======================

__global__ void k_stats(const float* __restrict__ x, float* __restrict__ mean,
                        float* __restrict__ stdv, float* __restrict__ xn) {
    int bm = blockIdx.x;
    int b = bm >> 5, m = bm & 31;
    int tid = threadIdx.x;
    float s = 0.f, sq = 0.f;
    for (int l = tid; l < Ll; l += 256) {
        float v = x[((size_t)b * Ll + l) * Mm + m];
        s += v; sq += v * v;
    }
    __shared__ float sh1[256], sh2[256];
    sh1[tid] = s; sh2[tid] = sq;
    __syncthreads();
    for (int o = 128; o; o >>= 1) {
        if (tid < o) { sh1[tid] += sh1[tid + o]; sh2[tid] += sh2[tid + o]; }
        __syncthreads();
    }
    __shared__ float smu, ssd;
    if (tid == 0) {
        float mu = sh1[0] / (float)Ll;
        float var = (sh2[0] - (float)Ll * mu * mu) / (float)(Ll - 1);
        if (var < 0.f) var = 0.f;
        float sd = sqrtf(var) + 1e-5f;
        smu = mu; ssd = sd;
        mean[bm] = mu; stdv[bm] = sd;
    }
    __syncthreads();
    float inv = 1.f / ssd;
    float mu = smu;
    for (int l = tid; l < Ll; l += 256) {
        xn[(size_t)bm * Ll + l] = (x[((size_t)b * Ll + l) * Mm + m] - mu) * inv;
    }
}

__global__ void k_patch(const float* __restrict__ xn, const float* __restrict__ pw,
                        const float* __restrict__ pb, const float* __restrict__ pos,
                        float* __restrict__ h) {
    int blk = blockIdx.x;
    int n = blk % Nn, bm = blk / Nn;
    int d = threadIdx.x;
    __shared__ float xs[Pp];
    if (d < Pp) xs[d] = xn[(size_t)bm * Ll + n * Sss + d];
    __syncthreads();
    float acc = pb[d];
#pragma unroll
    for (int p = 0; p < Pp; ++p) acc = fmaf(xs[p], pw[d * Pp + p], acc);
    acc += pos[n * Dd + d];
    h[(size_t)blk * Dd + d] = acc;
}

struct P5 { const float* p[5]; };

__global__ void k_combine(float* __restrict__ out, P5 pa, int na, const float* __restrict__ ra,
                          P5 pb, int nb, const float* __restrict__ rb, size_t n) {
    __shared__ float ca[5], cb[5];
    if (threadIdx.x == 0) {
        float mx = -1e30f;
        for (int i = 0; i < na; ++i) mx = fmaxf(mx, ra[i]);
        float s = 0.f;
        for (int i = 0; i < na; ++i) { ca[i] = __expf(ra[i] - mx); s += ca[i]; }
        for (int i = 0; i < na; ++i) ca[i] /= s;
        mx = -1e30f;
        for (int i = 0; i < nb; ++i) mx = fmaxf(mx, rb[i]);
        s = 0.f;
        for (int i = 0; i < nb; ++i) { cb[i] = __expf(rb[i] - mx); s += cb[i]; }
        for (int i = 0; i < nb; ++i) cb[i] /= s;
    }
    __syncthreads();
    for (size_t i = (size_t)blockIdx.x * blockDim.x + threadIdx.x; i < n;
         i += (size_t)gridDim.x * blockDim.x) {
        float acc = 0.f;
        for (int j = 0; j < na; ++j) acc = fmaf(ca[j], pa.p[j][i], acc);
        for (int j = 0; j < nb; ++j) acc = fmaf(cb[j], pb.p[j][i], acc);
        out[i] = acc;
    }
}

__global__ void k_ln(const float* __restrict__ x, const float* __restrict__ w,
                     const float* __restrict__ bia, float* __restrict__ out, int rows) {
    int warp = threadIdx.x >> 5, lane = threadIdx.x & 31;
    int row = blockIdx.x * 4 + warp;
    if (row >= rows) return;
    const float* xr = x + (size_t)row * Dd;
    float v0 = xr[lane], v1 = xr[lane + 32], v2 = xr[lane + 64], v3 = xr[lane + 96];
    float s = v0 + v1 + v2 + v3;
#pragma unroll
    for (int o = 16; o; o >>= 1) s += __shfl_xor_sync(0xffffffffu, s, o);
    float mu = s * (1.f / Dd);
    float d0 = v0 - mu, d1 = v1 - mu, d2 = v2 - mu, d3 = v3 - mu;
    float q = d0 * d0 + d1 * d1 + d2 * d2 + d3 * d3;
#pragma unroll
    for (int o = 16; o; o >>= 1) q += __shfl_xor_sync(0xffffffffu, q, o);
    float r = rsqrtf(q * (1.f / Dd) + 1e-5f);
    float* orow = out + (size_t)row * Dd;
    orow[lane]      = d0 * r * w[lane]      + bia[lane];
    orow[lane + 32] = d1 * r * w[lane + 32] + bia[lane + 32];
    orow[lane + 64] = d2 * r * w[lane + 64] + bia[lane + 64];
    orow[lane + 96] = d3 * r * w[lane + 96] + bia[lane + 96];
}

__global__ void k_lnT(const float* __restrict__ x, const float* __restrict__ w,
                      const float* __restrict__ bia, float* __restrict__ out) {
    int warp = threadIdx.x >> 5, lane = threadIdx.x & 31;
    int orow = blockIdx.x * 4 + warp;
    if (orow >= TT) return;
    int m = orow & 31;
    int bn = orow >> 5;
    int n = bn % Nn, b = bn / Nn;
    int irow = (b * Mm + m) * Nn + n;
    const float* xr = x + (size_t)irow * Dd;
    float v0 = xr[lane], v1 = xr[lane + 32], v2 = xr[lane + 64], v3 = xr[lane + 96];
    float s = v0 + v1 + v2 + v3;
#pragma unroll
    for (int o = 16; o; o >>= 1) s += __shfl_xor_sync(0xffffffffu, s, o);
    float mu = s * (1.f / Dd);
    float d0 = v0 - mu, d1 = v1 - mu, d2 = v2 - mu, d3 = v3 - mu;
    float q = d0 * d0 + d1 * d1 + d2 * d2 + d3 * d3;
#pragma unroll
    for (int o = 16; o; o >>= 1) q += __shfl_xor_sync(0xffffffffu, q, o);
    float r = rsqrtf(q * (1.f / Dd) + 1e-5f);
    float* orow_p = out + (size_t)orow * Dd;
    orow_p[lane]      = d0 * r * w[lane]      + bia[lane];
    orow_p[lane + 32] = d1 * r * w[lane + 32] + bia[lane + 32];
    orow_p[lane + 64] = d2 * r * w[lane + 64] + bia[lane + 64];
    orow_p[lane + 96] = d3 * r * w[lane + 96] + bia[lane + 96];
}

__global__ void k_transback(const float* __restrict__ chout, const float* __restrict__ chin,
                            float* __restrict__ out) {
    size_t total = (size_t)TT * Dd;
    for (size_t i = (size_t)blockIdx.x * blockDim.x + threadIdx.x; i < total;
         i += (size_t)gridDim.x * blockDim.x) {
        int d = (int)(i & 127);
        size_t rest = i >> 7;
        int n = (int)(rest % Nn);
        int bm = (int)(rest / Nn);
        int m = bm & 31, b = bm >> 5;
        size_t src = (((size_t)(b * Nn + n) * Mm + m) << 7) + d;
        out[i] = chout[src] + chin[i];
    }
}

__global__ void k_conv(const float* __restrict__ xz, const float* __restrict__ cw,
                       const float* __restrict__ cb, float* __restrict__ u,
                       int batch, int slen, int rev) {
    int idx = blockIdx.x * 256 + threadIdx.x;
    int total = batch * slen * DIi;
    if (idx >= total) return;
    int c = idx & 255;
    int row = idx >> 8;
    int s = row % slen, b = row / slen;
    float acc = cb[c];
#pragma unroll
    for (int k = 0; k < DCc; ++k) {
        int t = rev ? (s + 3 - k) : (s + k - 3);
        if (t >= 0 && t < slen)
            acc = fmaf(cw[c * DCc + k], xz[((size_t)(b * slen + t)) * (2 * DIi) + c], acc);
    }
    float sg = 1.f / (1.f + __expf(-acc));
    u[(size_t)row * DIi + c] = acc * sg;
}

__global__ void k_dt(const float* __restrict__ xdbl, const float* __restrict__ dtw,
                     const float* __restrict__ dtb, float* __restrict__ dt, int rows) {
    int idx = blockIdx.x * 256 + threadIdx.x;
    if (idx >= rows * DIi) return;
    int c = idx & 255;
    int row = idx >> 8;
    const float* xr = xdbl + (size_t)row * 40;
    float acc = dtb[c];
#pragma unroll
    for (int r = 0; r < DTRr; ++r) acc = fmaf(xr[r], dtw[c * DTRr + r], acc);
    float sp = (acc > 20.f) ? acc : log1pf(__expf(acc));
    dt[idx] = sp;
}

__global__ void k_scan(const float* __restrict__ dt, const float* __restrict__ u,
                       const float* __restrict__ xdbl, const float* __restrict__ xz,
                       const float* __restrict__ alog, const float* __restrict__ dssm,
                       float* __restrict__ y, int slen, int rev) {
    int b = blockIdx.x;
    int d = threadIdx.x;
    __shared__ float sBC[32];
    float a[NSTn];
#pragma unroll
    for (int n = 0; n < NSTn; ++n) a[n] = -__expf(alog[d * NSTn + n]);
    float a0 = a[0];
    bool geom = true;
#pragma unroll
    for (int n = 1; n < NSTn; ++n)
        geom = geom && (fabsf(a[n] - (float)(n + 1) * a0) <= 1e-4f * fabsf(a[n]));
    float dss = dssm[d];
    float h[NSTn];
#pragma unroll
    for (int n = 0; n < NSTn; ++n) h[n] = 0.f;

    for (int step = 0; step < slen; ++step) {
        int s = rev ? (slen - 1 - step) : step;
        size_t row = (size_t)b * slen + s;
        __syncthreads();
        if (d < 32) sBC[d] = xdbl[row * 40 + 8 + d];
        __syncthreads();
        float dtv = dt[row * DIi + d];
        float uv  = u[row * DIi + d];
        float du  = dtv * uv;
        float ysum = 0.f;
        if (geom) {
            float w = __expf(dtv * a0);
            float e = 1.f;
#pragma unroll
            for (int n = 0; n < NSTn; ++n) {
                e *= w;
                h[n] = fmaf(h[n], e, du * sBC[n]);
                ysum = fmaf(h[n], sBC[16 + n], ysum);
            }
        } else {
#pragma unroll
            for (int n = 0; n < NSTn; ++n) {
                float e = __expf(dtv * a[n]);
                h[n] = fmaf(h[n], e, du * sBC[n]);
                ysum = fmaf(h[n], sBC[16 + n], ysum);
            }
        }
        float zv = xz[row * (2 * DIi) + DIi + d];
        float sg = 1.f / (1.f + __expf(-zv));
        y[row * DIi + d] = (ysum + uv * dss) * (zv * sg);
    }
}

__global__ void k_ln_n(const float* __restrict__ x, const float* __restrict__ w2,
                       const float* __restrict__ b2, float* __restrict__ out) {
    int idx = blockIdx.x * 256 + threadIdx.x;
    if (idx >= BMr * Dd) return;
    int d = idx & 127, bm = idx >> 7;
    const float* base = x + (size_t)bm * Nn * Dd + d;
    float s = 0.f, q = 0.f;
    for (int n = 0; n < Nn; ++n) { float v = base[(size_t)n * Dd]; s += v; q += v * v; }
    float mu = s * (1.f / Nn);
    float var = q * (1.f / Nn) - mu * mu;
    if (var < 0.f) var = 0.f;
    float r = rsqrtf(var + 1e-5f);
    float* ob = out + (size_t)bm * Nn * Dd + d;
    for (int n = 0; n < Nn; ++n)
        ob[(size_t)n * Dd] = (base[(size_t)n * Dd] - mu) * r * w2[n] + b2[n];
}

__global__ void k_headep(const float* __restrict__ hv, const float* __restrict__ hb,
                         const float* __restrict__ mean, const float* __restrict__ stdv,
                         float* __restrict__ out) {
    int idx = blockIdx.x * 256 + threadIdx.x;
    if (idx >= Bb * PREDp * Mm) return;
    int m = idx % Mm;
    int p = (idx / Mm) % PREDp;
    int b = idx / (Mm * PREDp);
    int bm = b * Mm + m;
    out[idx] = (hv[(size_t)bm * PREDp + p] + hb[p]) * stdv[bm] + mean[bm];
}

// ======================= host orchestration =======================

extern "C" void kernel_launch(void* const* d_in, const int* in_sizes, int n_in,
                              void* d_out, int out_size) {
    (void)in_sizes; (void)n_in; (void)out_size;
    const float* x      = (const float*)d_in[0];
    const float* patchw = (const float*)d_in[1];
    const float* patchb = (const float*)d_in[2];
    const float* pos    = (const float*)d_in[3];
    const float* alpha  = (const float*)d_in[4];
    const float* beta   = (const float*)d_in[5];
    const float* theta  = (const float*)d_in[6];
    const float* gma    = (const float*)d_in[7];
    const float* tnw    = (const float*)d_in[8];
    const float* tnb    = (const float*)d_in[9];
    const float* cnw    = (const float*)d_in[10];
    const float* cnb    = (const float*)d_in[11];
    const float* inw    = (const float*)d_in[12];
    const float* cvw    = (const float*)d_in[13];
    const float* cvb    = (const float*)d_in[14];
    const float* xpw    = (const float*)d_in[15];
    const float* dtw    = (const float*)d_in[16];
    const float* dtbv   = (const float*)d_in[17];
    const float* alog   = (const float*)d_in[18];
    const float* dssm   = (const float*)d_in[19];
    const float* outw   = (const float*)d_in[20];
    const float* n2w1   = (const float*)d_in[21];
    const float* n2b1   = (const float*)d_in[22];
    const float* n2w2   = (const float*)d_in[23];
    const float* n2b2   = (const float*)d_in[24];
    const float* headw  = (const float*)d_in[25];
    const float* headb  = (const float*)d_in[26];

    float *p_y, *p_xn, *p_mean, *p_std, *p_tokin, *p_norm, *p_chr, *p_chout;
    float *p_xz, *p_u, *p_dt, *p_xdbl, *p_ys, *p_tmp, *p_head;
    cudaGetSymbolAddress((void**)&p_y,     g_y);
    cudaGetSymbolAddress((void**)&p_xn,    g_xn);
    cudaGetSymbolAddress((void**)&p_mean,  g_mean);
    cudaGetSymbolAddress((void**)&p_std,   g_std);
    cudaGetSymbolAddress((void**)&p_tokin, g_tokin);
    cudaGetSymbolAddress((void**)&p_norm,  g_norm);
    cudaGetSymbolAddress((void**)&p_chr,   g_chr);
    cudaGetSymbolAddress((void**)&p_chout, g_chout);
    cudaGetSymbolAddress((void**)&p_xz,    g_xz);
    cudaGetSymbolAddress((void**)&p_u,     g_u);
    cudaGetSymbolAddress((void**)&p_dt,    g_dtv);
    cudaGetSymbolAddress((void**)&p_xdbl,  g_xdbl);
    cudaGetSymbolAddress((void**)&p_ys,    g_ys);
    cudaGetSymbolAddress((void**)&p_tmp,   g_tmp);
    cudaGetSymbolAddress((void**)&p_head,  g_head);

    float* yT[5]; float* yC[5];
    yT[0] = p_y; yC[0] = p_y;
    for (int i = 1; i <= 4; ++i) {
        yT[i] = p_y + (size_t)i * TT * Dd;
        yC[i] = p_y + (size_t)(4 + i) * TT * Dd;
    }

    k_stats<<<BMr, 256>>>(x, p_mean, p_std, p_xn);
    k_patch<<<TT, Dd>>>(p_xn, patchw, patchb, pos, p_y);

    const size_t NE = (size_t)TT * Dd;
    const int cgrid = 4096;
    const int GY = TT / 128;   // 252

    auto mamba = [&](const float* inp, int batch, int slen, int l, int r,
                     const float* resid, float* outp, int flags, int rev) {
        int rows = batch * slen;       // 32256
        size_t lr = (size_t)(l * 3 + r);
        k_mma<512><<<dim3(8, GY), 256>>>(inp, inw + lr * 2 * DIi * Dd, p_xz,
                                         nullptr, Dd, 0);
        k_conv<<<(rows * DIi + 255) / 256, 256>>>(p_xz, cvw + lr * DIi * DCc, cvb + lr * DIi,
                                                  p_u, batch, slen, rev);
        k_mma<40><<<dim3(1, GY), 256>>>(p_u, xpw + lr * 40 * DIi, p_xdbl,
                                        nullptr, DIi, 0);
        k_dt<<<(rows * DIi + 255) / 256, 256>>>(p_xdbl, dtw + lr * DIi * DTRr, dtbv + lr * DIi,
                                                p_dt, rows);
        k_scan<<<batch, DIi>>>(p_dt, p_u, p_xdbl, p_xz, alog + lr * DIi * NSTn, dssm + lr * DIi,
                               p_ys, slen, rev);
        k_mma<128><<<dim3(2, GY), 256>>>(p_ys, outw + lr * Dd * DIi, outp,
                                         resid, DIi, flags);
    };

    for (int l = 0; l < NLl; ++l) {
        P5 pa = {}, pb = {};
        for (int i = 0; i <= l; ++i) { pa.p[i] = yT[i]; pb.p[i] = yC[i]; }
        k_combine<<<cgrid, 256>>>(p_tokin, pa, l + 1, alpha + l * NLl,
                                  pb, l + 1, beta + l * NLl, NE);
        k_ln<<<TT / 4, 128>>>(p_tokin, tnw + l * Dd, tnb + l * Dd, p_norm, TT);
        mamba(p_norm, BMr, Nn, l, 0, p_tokin, yT[l + 1], 2, 0);

        P5 pc = {}, pd = {};
        for (int i = 0; i <= l + 1; ++i) pc.p[i] = yT[i];
        for (int i = 0; i <= l; ++i)     pd.p[i] = yC[i];
        k_combine<<<cgrid, 256>>>(p_tokin, pc, l + 2, theta + l * (NLl + 1),
                                  pd, l + 1, gma + l * NLl, NE);
        k_lnT<<<TT / 4, 128>>>(p_tokin, cnw + l * Dd, cnb + l * Dd, p_chr);
        mamba(p_chr, BNb, Mm, l, 1, nullptr, p_chout, 0, 0);
        mamba(p_chr, BNb, Mm, l, 2, nullptr, p_chout, 1, 1);
        k_transback<<<cgrid, 256>>>(p_chout, p_tokin, yC[l + 1]);
    }

    k_ln<<<TT / 4, 128>>>(yC[4], n2w1, n2b1, p_tmp, TT);
    k_ln_n<<<(BMr * Dd + 255) / 256, 256>>>(p_tmp, n2w2, n2b2, p_norm);
    k_mma<96><<<dim3(2, 4), 256>>>(p_norm, headw, p_head, nullptr, Nn * Dd, 0);
    k_headep<<<(Bb * PREDp * Mm + 255) / 256, 256>>>(p_head, headb, p_mean, p_std,
                                                     (float*)d_out);
}

// round 4
// speedup vs baseline: 1.8615x; 1.2010x over previous
#include <cuda_runtime.h>
#include <cuda_bf16.h>
#include <math.h>
#include <stdint.h>

// ---- problem dims ----
#define Bb   16
#define Ll   512
#define Mm   32
#define PREDp 96
#define Pp   16
#define Sss  8
#define Dd   128
#define NSTn 16
#define DCc  4
#define NLl  4
#define Nn   63
#define DIi  256
#define DTRr 8
#define BMr  512
#define TT   32256        // = 512*63 = 1008*32 = 252*128
#define BNb  1008
#define KSPLIT 21         // head GEMM split-K slices (8064 = 21*384)

// ---- static device scratch ----
__device__ float g_y[9][(size_t)TT * Dd];
__device__ float g_xn[(size_t)BMr * Ll];
__device__ float g_mean[BMr];
__device__ float g_std[BMr];
__device__ float g_tokin[(size_t)TT * Dd];
__device__ float g_norm[(size_t)TT * Dd];
__device__ float g_chr[(size_t)TT * Dd];
__device__ float g_chout[(size_t)TT * Dd];
__device__ float g_xz[(size_t)TT * 2 * DIi];
__device__ float g_ys[(size_t)TT * DIi];
__device__ float g_tmp[(size_t)TT * Dd];
__device__ float g_headp[(size_t)KSPLIT * BMr * PREDp];

// ======================= warp-mma bf16-split GEMM =======================
// C[M,NT] = A[M,K] @ Bw[NT,K]^T, fp32 in/out, bf16 hi/lo split (3 HMMA terms).
// grid = (ceil(NT/64), M/128, nsplit), block = 256 (8 warps of 32x32 tiles).
// Each z-slice covers klen of K and writes to its own C slice (split-K).
// flags: 1 = accumulate into C, 2 = add R. klen % 32 == 0.

#define SASTR 40   // smem row stride (bf16), padded for conflict-free frags

__device__ __forceinline__ void mma16816(float* d, const uint32_t* a, const uint32_t* b) {
    asm volatile(
        "mma.sync.aligned.m16n8k16.row.col.f32.bf16.bf16.f32 "
        "{%0,%1,%2,%3},{%4,%5,%6,%7},{%8,%9},{%0,%1,%2,%3};"
        : "+f"(d[0]), "+f"(d[1]), "+f"(d[2]), "+f"(d[3])
        : "r"(a[0]), "r"(a[1]), "r"(a[2]), "r"(a[3]), "r"(b[0]), "r"(b[1]));
}

union BH2 { __nv_bfloat16 h[2]; uint32_t u; };

template <int NT>
__global__ __launch_bounds__(256) void k_mma(const float* __restrict__ A,
                                             const float* __restrict__ Bw,
                                             float* __restrict__ C,
                                             const float* __restrict__ R,
                                             int K, int klen, int flags) {
    __shared__ __nv_bfloat16 sA[2][128 * SASTR];
    __shared__ __nv_bfloat16 sB[2][64 * SASTR];

    int tid = threadIdx.x;
    int warp = tid >> 5, lane = tid & 31;
    int gq = lane >> 2, tig = lane & 3;
    int warpM = warp >> 1, warpN = warp & 1;
    int m0 = blockIdx.y * 128;
    int n0 = blockIdx.x * 64;
    int kbeg = blockIdx.z * klen;
    C += (size_t)blockIdx.z * ((size_t)gridDim.y * 128) * NT;

    float acc[2][4][4];
#pragma unroll
    for (int i = 0; i < 2; ++i)
#pragma unroll
        for (int j = 0; j < 4; ++j)
#pragma unroll
            for (int r = 0; r < 4; ++r) acc[i][j][r] = 0.f;

    float4 ra[4], rb[2];

    auto ldA = [&](int k0) {
#pragma unroll
        for (int t = 0; t < 4; ++t) {
            int gg = tid + t * 256;
            int row = gg >> 3, c = (gg & 7) << 2;
            ra[t] = *reinterpret_cast<const float4*>(A + (size_t)(m0 + row) * K + k0 + c);
        }
    };
    auto ldB = [&](int k0) {
#pragma unroll
        for (int t = 0; t < 2; ++t) {
            int gg = tid + t * 256;
            int row = gg >> 3, c = (gg & 7) << 2;
            int grow = n0 + row;
            if ((NT & 63) == 0 || grow < NT)
                rb[t] = *reinterpret_cast<const float4*>(Bw + (size_t)grow * K + k0 + c);
            else
                rb[t] = make_float4(0.f, 0.f, 0.f, 0.f);
        }
    };

    ldA(kbeg); ldB(kbeg);
    int nch = klen >> 5;
    for (int ch = 0; ch < nch; ++ch) {
#pragma unroll
        for (int t = 0; t < 4; ++t) {
            int gg = tid + t * 256;
            int row = gg >> 3, c = (gg & 7) << 2;
            float v[4] = {ra[t].x, ra[t].y, ra[t].z, ra[t].w};
            BH2 h0, h1, l0, l1;
#pragma unroll
            for (int q = 0; q < 2; ++q) {
                h0.h[q] = __float2bfloat16(v[q]);
                l0.h[q] = __float2bfloat16(v[q] - __bfloat162float(h0.h[q]));
                h1.h[q] = __float2bfloat16(v[2 + q]);
                l1.h[q] = __float2bfloat16(v[2 + q] - __bfloat162float(h1.h[q]));
            }
            uint32_t* ph = reinterpret_cast<uint32_t*>(&sA[0][row * SASTR + c]);
            uint32_t* pl = reinterpret_cast<uint32_t*>(&sA[1][row * SASTR + c]);
            ph[0] = h0.u; ph[1] = h1.u; pl[0] = l0.u; pl[1] = l1.u;
        }
#pragma unroll
        for (int t = 0; t < 2; ++t) {
            int gg = tid + t * 256;
            int row = gg >> 3, c = (gg & 7) << 2;
            float v[4] = {rb[t].x, rb[t].y, rb[t].z, rb[t].w};
            BH2 h0, h1, l0, l1;
#pragma unroll
            for (int q = 0; q < 2; ++q) {
                h0.h[q] = __float2bfloat16(v[q]);
                l0.h[q] = __float2bfloat16(v[q] - __bfloat162float(h0.h[q]));
                h1.h[q] = __float2bfloat16(v[2 + q]);
                l1.h[q] = __float2bfloat16(v[2 + q] - __bfloat162float(h1.h[q]));
            }
            uint32_t* ph = reinterpret_cast<uint32_t*>(&sB[0][row * SASTR + c]);
            uint32_t* pl = reinterpret_cast<uint32_t*>(&sB[1][row * SASTR + c]);
            ph[0] = h0.u; ph[1] = h1.u; pl[0] = l0.u; pl[1] = l1.u;
        }
        __syncthreads();
        if (ch + 1 < nch) { ldA(kbeg + ((ch + 1) << 5)); ldB(kbeg + ((ch + 1) << 5)); }

#pragma unroll
        for (int kk = 0; kk < 2; ++kk) {
            int kb = kk * 16 + 2 * tig;
            uint32_t ah[2][4], al[2][4];
#pragma unroll
            for (int i = 0; i < 2; ++i) {
                int r0 = warpM * 32 + i * 16 + gq;
                const uint32_t* p0h = reinterpret_cast<const uint32_t*>(&sA[0][r0 * SASTR + kb]);
                const uint32_t* p1h = reinterpret_cast<const uint32_t*>(&sA[0][(r0 + 8) * SASTR + kb]);
                const uint32_t* p0l = reinterpret_cast<const uint32_t*>(&sA[1][r0 * SASTR + kb]);
                const uint32_t* p1l = reinterpret_cast<const uint32_t*>(&sA[1][(r0 + 8) * SASTR + kb]);
                ah[i][0] = p0h[0]; ah[i][1] = p1h[0]; ah[i][2] = p0h[4]; ah[i][3] = p1h[4];
                al[i][0] = p0l[0]; al[i][1] = p1l[0]; al[i][2] = p0l[4]; al[i][3] = p1l[4];
            }
            uint32_t bh[4][2], bl[4][2];
#pragma unroll
            for (int j = 0; j < 4; ++j) {
                int n = warpN * 32 + j * 8 + gq;
                const uint32_t* pbh = reinterpret_cast<const uint32_t*>(&sB[0][n * SASTR + kb]);
                const uint32_t* pbl = reinterpret_cast<const uint32_t*>(&sB[1][n * SASTR + kb]);
                bh[j][0] = pbh[0]; bh[j][1] = pbh[4];
                bl[j][0] = pbl[0]; bl[j][1] = pbl[4];
            }
#pragma unroll
            for (int i = 0; i < 2; ++i)
#pragma unroll
                for (int j = 0; j < 4; ++j) {
                    mma16816(acc[i][j], ah[i], bh[j]);
                    mma16816(acc[i][j], ah[i], bl[j]);
                    mma16816(acc[i][j], al[i], bh[j]);
                }
        }
        __syncthreads();
    }

#pragma unroll
    for (int i = 0; i < 2; ++i) {
        int grow = m0 + warpM * 32 + i * 16 + gq;
#pragma unroll
        for (int j = 0; j < 4; ++j) {
            int gcol = n0 + warpN * 32 + j * 8 + 2 * tig;
            if ((NT & 63) != 0 && gcol >= NT) continue;
            size_t o0 = (size_t)grow * NT + gcol;
            size_t o1 = (size_t)(grow + 8) * NT + gcol;
            float2 v0 = make_float2(acc[i][j][0], acc[i][j][1]);
            float2 v1 = make_float2(acc[i][j][2], acc[i][j][3]);
            if (flags & 2) {
                float2 t0 = *reinterpret_cast<const float2*>(R + o0);
                float2 t1 = *reinterpret_cast<const float2*>(R + o1);
                v0.x += t0.x; v0.y += t0.y; v1.x += t1.x; v1.y += t1.y;
            }
            if (flags & 1) {
                float2 t0 = *reinterpret_cast<const float2*>(C + o0);
                float2 t1 = *reinterpret_cast<const float2*>(C + o1);
                v0.x += t0.x; v0.y += t0.y; v1.x += t1.x; v1.y += t1.y;
            }
            *reinterpret_cast<float2*>(C + o0) = v0;
            *reinterpret_cast<float2*>(C + o1) = v1;
        }
    }
}

// ======================= fused conv+x_proj+dt+scan =======================
// One block per sequence, 256 threads = DI channels. Reads xz (xi|z), writes ys.
__global__ __launch_bounds__(256) void k_fscan(
    const float* __restrict__ xz, const float* __restrict__ xw,
    const float* __restrict__ dtw, const float* __restrict__ dtb,
    const float* __restrict__ cw, const float* __restrict__ cb,
    const float* __restrict__ alog, const float* __restrict__ dssm,
    float* __restrict__ y, int slen, int rev) {
    __shared__ float sW[40 * DIi];
    __shared__ float ring[4][DIi];
    __shared__ float su[DIi];
    __shared__ float sx[40];

    int c = threadIdx.x;
    int warp = c >> 5, lane = c & 31;
    int b = blockIdx.x;

    for (int i = c; i < 40 * DIi; i += 256) sW[i] = xw[i];

    float dtwr[DTRr];
#pragma unroll
    for (int r = 0; r < DTRr; ++r) dtwr[r] = dtw[c * DTRr + r];
    float dtbr = dtb[c];
    float cwr[4];
#pragma unroll
    for (int k = 0; k < 4; ++k) cwr[k] = cw[c * 4 + k];
    float cbr = cb[c];
    float dss = dssm[c];

    float a[NSTn];
#pragma unroll
    for (int n = 0; n < NSTn; ++n) a[n] = -__expf(alog[c * NSTn + n]);
    float a0 = a[0];
    bool geom = true;
#pragma unroll
    for (int n = 1; n < NSTn; ++n)
        geom = geom && (fabsf(a[n] - (float)(n + 1) * a0) <= 1e-4f * fabsf(a[n]));
    float h[NSTn];
#pragma unroll
    for (int n = 0; n < NSTn; ++n) h[n] = 0.f;

    __syncthreads();

    size_t base = (size_t)b * slen;
    int s0 = rev ? slen - 1 : 0;
    float xi_nx = xz[(base + s0) * (2 * DIi) + c];
    float z_nx  = xz[(base + s0) * (2 * DIi) + DIi + c];

    for (int step = 0; step < slen; ++step) {
        int s = rev ? slen - 1 - step : step;
        ring[s & 3][c] = xi_nx;
        float zv = z_nx;
        __syncthreads();
        if (step + 1 < slen) {
            int sn = rev ? s - 1 : s + 1;
            xi_nx = xz[(base + sn) * (2 * DIi) + c];
            z_nx  = xz[(base + sn) * (2 * DIi) + DIi + c];
        }
        // depthwise conv + SiLU
        float acc = cbr;
#pragma unroll
        for (int k = 0; k < 4; ++k) {
            int t = rev ? (s + 3 - k) : (s + k - 3);
            if (t >= 0 && t < slen) acc = fmaf(cwr[k], ring[t & 3][c], acc);
        }
        float uv = acc / (1.f + __expf(-acc));
        su[c] = uv;
        __syncthreads();
        // x_proj matvec: 8 warps x 5 outputs
#pragma unroll
        for (int oo = 0; oo < 5; ++oo) {
            int o = warp * 5 + oo;
            const float* wr = &sW[o * DIi];
            float p = 0.f;
#pragma unroll
            for (int k8 = 0; k8 < 8; ++k8)
                p = fmaf(su[lane + 32 * k8], wr[lane + 32 * k8], p);
#pragma unroll
            for (int off = 16; off; off >>= 1) p += __shfl_xor_sync(0xffffffffu, p, off);
            if (lane == 0) sx[o] = p;
        }
        __syncthreads();
        // dt projection + softplus
        float dtacc = dtbr;
#pragma unroll
        for (int r = 0; r < DTRr; ++r) dtacc = fmaf(sx[r], dtwr[r], dtacc);
        float dtv = (dtacc > 20.f) ? dtacc : log1pf(__expf(dtacc));
        float du = dtv * uv;
        float ysum = 0.f;
        if (geom) {
            float w = __expf(dtv * a0);
            float e = 1.f;
#pragma unroll
            for (int n = 0; n < NSTn; ++n) {
                e *= w;
                h[n] = fmaf(h[n], e, du * sx[8 + n]);
                ysum = fmaf(h[n], sx[24 + n], ysum);
            }
        } else {
#pragma unroll
            for (int n = 0; n < NSTn; ++n) {
                float e = __expf(dtv * a[n]);
                h[n] = fmaf(h[n], e, du * sx[8 + n]);
                ysum = fmaf(h[n], sx[24 + n], ysum);
            }
        }
        float sg = 1.f / (1.f + __expf(-zv));
        y[(base + s) * DIi + c] = (ysum + uv * dss) * (zv * sg);
    }
}

// ======================= fused combine + LN (+transpose) =======================
struct P5 { const float* p[5]; };

template <int TRANS>
__global__ void k_combineln(P5 pa, int na, const float* __restrict__ ra,
                            P5 pb, int nb, const float* __restrict__ rb,
                            const float* __restrict__ w, const float* __restrict__ bia,
                            float* __restrict__ comb, float* __restrict__ normout) {
    __shared__ float ca[5], cb2[5];
    if (threadIdx.x == 0) {
        float mx = -1e30f;
        for (int i = 0; i < na; ++i) mx = fmaxf(mx, ra[i]);
        float s = 0.f;
        for (int i = 0; i < na; ++i) { ca[i] = __expf(ra[i] - mx); s += ca[i]; }
        for (int i = 0; i < na; ++i) ca[i] /= s;
        mx = -1e30f;
        for (int i = 0; i < nb; ++i) mx = fmaxf(mx, rb[i]);
        s = 0.f;
        for (int i = 0; i < nb; ++i) { cb2[i] = __expf(rb[i] - mx); s += cb2[i]; }
        for (int i = 0; i < nb; ++i) cb2[i] /= s;
    }
    __syncthreads();
    int warp = threadIdx.x >> 5, lane = threadIdx.x & 31;
    int row = blockIdx.x * 4 + warp;
    if (row >= TT) return;
    int irow = row;
    if (TRANS) {
        int m = row & 31;
        int bn = row >> 5;
        int n = bn % Nn, b = bn / Nn;
        irow = (b * Mm + m) * Nn + n;
    }
    float v[4];
#pragma unroll
    for (int q = 0; q < 4; ++q) {
        size_t off = (size_t)irow * Dd + lane + 32 * q;
        float acc = 0.f;
        for (int j = 0; j < na; ++j) acc = fmaf(ca[j], pa.p[j][off], acc);
        for (int j = 0; j < nb; ++j) acc = fmaf(cb2[j], pb.p[j][off], acc);
        v[q] = acc;
        comb[off] = acc;
    }
    float s = v[0] + v[1] + v[2] + v[3];
#pragma unroll
    for (int o = 16; o; o >>= 1) s += __shfl_xor_sync(0xffffffffu, s, o);
    float mu = s * (1.f / Dd);
    float q0 = 0.f;
#pragma unroll
    for (int q = 0; q < 4; ++q) { v[q] -= mu; q0 += v[q] * v[q]; }
#pragma unroll
    for (int o = 16; o; o >>= 1) q0 += __shfl_xor_sync(0xffffffffu, q0, o);
    float r = rsqrtf(q0 * (1.f / Dd) + 1e-5f);
    float* orow = normout + (size_t)row * Dd;
#pragma unroll
    for (int q = 0; q < 4; ++q) {
        int e = lane + 32 * q;
        orow[e] = v[q] * r * w[e] + bia[e];
    }
}

// ======================= other supporting kernels =======================

__global__ void k_stats(const float* __restrict__ x, float* __restrict__ mean,
                        float* __restrict__ stdv, float* __restrict__ xn) {
    int bm = blockIdx.x;
    int b = bm >> 5, m = bm & 31;
    int tid = threadIdx.x;
    float s = 0.f, sq = 0.f;
    for (int l = tid; l < Ll; l += 256) {
        float v = x[((size_t)b * Ll + l) * Mm + m];
        s += v; sq += v * v;
    }
    __shared__ float sh1[256], sh2[256];
    sh1[tid] = s; sh2[tid] = sq;
    __syncthreads();
    for (int o = 128; o; o >>= 1) {
        if (tid < o) { sh1[tid] += sh1[tid + o]; sh2[tid] += sh2[tid + o]; }
        __syncthreads();
    }
    __shared__ float smu, ssd;
    if (tid == 0) {
        float mu = sh1[0] / (float)Ll;
        float var = (sh2[0] - (float)Ll * mu * mu) / (float)(Ll - 1);
        if (var < 0.f) var = 0.f;
        float sd = sqrtf(var) + 1e-5f;
        smu = mu; ssd = sd;
        mean[bm] = mu; stdv[bm] = sd;
    }
    __syncthreads();
    float inv = 1.f / ssd;
    float mu = smu;
    for (int l = tid; l < Ll; l += 256) {
        xn[(size_t)bm * Ll + l] = (x[((size_t)b * Ll + l) * Mm + m] - mu) * inv;
    }
}

__global__ void k_patch(const float* __restrict__ xn, const float* __restrict__ pw,
                        const float* __restrict__ pb, const float* __restrict__ pos,
                        float* __restrict__ h) {
    int blk = blockIdx.x;
    int n = blk % Nn, bm = blk / Nn;
    int d = threadIdx.x;
    __shared__ float xs[Pp];
    if (d < Pp) xs[d] = xn[(size_t)bm * Ll + n * Sss + d];
    __syncthreads();
    float acc = pb[d];
#pragma unroll
    for (int p = 0; p < Pp; ++p) acc = fmaf(xs[p], pw[d * Pp + p], acc);
    acc += pos[n * Dd + d];
    h[(size_t)blk * Dd + d] = acc;
}

__global__ void k_ln(const float* __restrict__ x, const float* __restrict__ w,
                     const float* __restrict__ bia, float* __restrict__ out, int rows) {
    int warp = threadIdx.x >> 5, lane = threadIdx.x & 31;
    int row = blockIdx.x * 4 + warp;
    if (row >= rows) return;
    const float* xr = x + (size_t)row * Dd;
    float v0 = xr[lane], v1 = xr[lane + 32], v2 = xr[lane + 64], v3 = xr[lane + 96];
    float s = v0 + v1 + v2 + v3;
#pragma unroll
    for (int o = 16; o; o >>= 1) s += __shfl_xor_sync(0xffffffffu, s, o);
    float mu = s * (1.f / Dd);
    float d0 = v0 - mu, d1 = v1 - mu, d2 = v2 - mu, d3 = v3 - mu;
    float q = d0 * d0 + d1 * d1 + d2 * d2 + d3 * d3;
#pragma unroll
    for (int o = 16; o; o >>= 1) q += __shfl_xor_sync(0xffffffffu, q, o);
    float r = rsqrtf(q * (1.f / Dd) + 1e-5f);
    float* orow = out + (size_t)row * Dd;
    orow[lane]      = d0 * r * w[lane]      + bia[lane];
    orow[lane + 32] = d1 * r * w[lane + 32] + bia[lane + 32];
    orow[lane + 64] = d2 * r * w[lane + 64] + bia[lane + 64];
    orow[lane + 96] = d3 * r * w[lane + 96] + bia[lane + 96];
}

__global__ void k_transback(const float* __restrict__ chout, const float* __restrict__ chin,
                            float* __restrict__ out) {
    size_t total = (size_t)TT * Dd;
    for (size_t i = (size_t)blockIdx.x * blockDim.x + threadIdx.x; i < total;
         i += (size_t)gridDim.x * blockDim.x) {
        int d = (int)(i & 127);
        size_t rest = i >> 7;
        int n = (int)(rest % Nn);
        int bm = (int)(rest / Nn);
        int m = bm & 31, b = bm >> 5;
        size_t src = (((size_t)(b * Nn + n) * Mm + m) << 7) + d;
        out[i] = chout[src] + chin[i];
    }
}

__global__ void k_ln_n(const float* __restrict__ x, const float* __restrict__ w2,
                       const float* __restrict__ b2, float* __restrict__ out) {
    int idx = blockIdx.x * 256 + threadIdx.x;
    if (idx >= BMr * Dd) return;
    int d = idx & 127, bm = idx >> 7;
    const float* base = x + (size_t)bm * Nn * Dd + d;
    float s = 0.f, q = 0.f;
    for (int n = 0; n < Nn; ++n) { float v = base[(size_t)n * Dd]; s += v; q += v * v; }
    float mu = s * (1.f / Nn);
    float var = q * (1.f / Nn) - mu * mu;
    if (var < 0.f) var = 0.f;
    float r = rsqrtf(var + 1e-5f);
    float* ob = out + (size_t)bm * Nn * Dd + d;
    for (int n = 0; n < Nn; ++n)
        ob[(size_t)n * Dd] = (base[(size_t)n * Dd] - mu) * r * w2[n] + b2[n];
}

// split-K reduce + head bias + de-normalization epilogue
__global__ void k_headred(const float* __restrict__ hp, const float* __restrict__ hb,
                          const float* __restrict__ mean, const float* __restrict__ stdv,
                          float* __restrict__ out) {
    int idx = blockIdx.x * 256 + threadIdx.x;
    if (idx >= Bb * PREDp * Mm) return;
    int m = idx % Mm;
    int p = (idx / Mm) % PREDp;
    int b = idx / (Mm * PREDp);
    int bm = b * Mm + m;
    float s = 0.f;
#pragma unroll 3
    for (int z = 0; z < KSPLIT; ++z)
        s += hp[(size_t)z * BMr * PREDp + (size_t)bm * PREDp + p];
    out[idx] = (s + hb[p]) * stdv[bm] + mean[bm];
}

// ======================= host orchestration =======================

extern "C" void kernel_launch(void* const* d_in, const int* in_sizes, int n_in,
                              void* d_out, int out_size) {
    (void)in_sizes; (void)n_in; (void)out_size;
    const float* x      = (const float*)d_in[0];
    const float* patchw = (const float*)d_in[1];
    const float* patchb = (const float*)d_in[2];
    const float* pos    = (const float*)d_in[3];
    const float* alpha  = (const float*)d_in[4];
    const float* beta   = (const float*)d_in[5];
    const float* theta  = (const float*)d_in[6];
    const float* gma    = (const float*)d_in[7];
    const float* tnw    = (const float*)d_in[8];
    const float* tnb    = (const float*)d_in[9];
    const float* cnw    = (const float*)d_in[10];
    const float* cnb    = (const float*)d_in[11];
    const float* inw    = (const float*)d_in[12];
    const float* cvw    = (const float*)d_in[13];
    const float* cvb    = (const float*)d_in[14];
    const float* xpw    = (const float*)d_in[15];
    const float* dtw    = (const float*)d_in[16];
    const float* dtbv   = (const float*)d_in[17];
    const float* alog   = (const float*)d_in[18];
    const float* dssm   = (const float*)d_in[19];
    const float* outw   = (const float*)d_in[20];
    const float* n2w1   = (const float*)d_in[21];
    const float* n2b1   = (const float*)d_in[22];
    const float* n2w2   = (const float*)d_in[23];
    const float* n2b2   = (const float*)d_in[24];
    const float* headw  = (const float*)d_in[25];
    const float* headb  = (const float*)d_in[26];

    float *p_y, *p_xn, *p_mean, *p_std, *p_tokin, *p_norm, *p_chr, *p_chout;
    float *p_xz, *p_ys, *p_tmp, *p_headp;
    cudaGetSymbolAddress((void**)&p_y,     g_y);
    cudaGetSymbolAddress((void**)&p_xn,    g_xn);
    cudaGetSymbolAddress((void**)&p_mean,  g_mean);
    cudaGetSymbolAddress((void**)&p_std,   g_std);
    cudaGetSymbolAddress((void**)&p_tokin, g_tokin);
    cudaGetSymbolAddress((void**)&p_norm,  g_norm);
    cudaGetSymbolAddress((void**)&p_chr,   g_chr);
    cudaGetSymbolAddress((void**)&p_chout, g_chout);
    cudaGetSymbolAddress((void**)&p_xz,    g_xz);
    cudaGetSymbolAddress((void**)&p_ys,    g_ys);
    cudaGetSymbolAddress((void**)&p_tmp,   g_tmp);
    cudaGetSymbolAddress((void**)&p_headp, g_headp);

    float* yT[5]; float* yC[5];
    yT[0] = p_y; yC[0] = p_y;
    for (int i = 1; i <= 4; ++i) {
        yT[i] = p_y + (size_t)i * TT * Dd;
        yC[i] = p_y + (size_t)(4 + i) * TT * Dd;
    }

    k_stats<<<BMr, 256>>>(x, p_mean, p_std, p_xn);
    k_patch<<<TT, Dd>>>(p_xn, patchw, patchb, pos, p_y);

    const int GY = TT / 128;   // 252

    auto mamba = [&](const float* inp, int batch, int slen, int l, int r,
                     const float* resid, float* outp, int flags, int rev) {
        size_t lr = (size_t)(l * 3 + r);
        k_mma<512><<<dim3(8, GY, 1), 256>>>(inp, inw + lr * 2 * DIi * Dd, p_xz,
                                            nullptr, Dd, Dd, 0);
        k_fscan<<<batch, 256>>>(p_xz, xpw + lr * 40 * DIi, dtw + lr * DIi * DTRr,
                                dtbv + lr * DIi, cvw + lr * DIi * DCc, cvb + lr * DIi,
                                alog + lr * DIi * NSTn, dssm + lr * DIi,
                                p_ys, slen, rev);
        k_mma<128><<<dim3(2, GY, 1), 256>>>(p_ys, outw + lr * Dd * DIi, outp,
                                            resid, DIi, DIi, flags);
    };

    for (int l = 0; l < NLl; ++l) {
        P5 pa = {}, pb = {};
        for (int i = 0; i <= l; ++i) { pa.p[i] = yT[i]; pb.p[i] = yC[i]; }
        k_combineln<0><<<TT / 4, 128>>>(pa, l + 1, alpha + l * NLl,
                                        pb, l + 1, beta + l * NLl,
                                        tnw + l * Dd, tnb + l * Dd, p_tokin, p_norm);
        mamba(p_norm, BMr, Nn, l, 0, p_tokin, yT[l + 1], 2, 0);

        P5 pc = {}, pd = {};
        for (int i = 0; i <= l + 1; ++i) pc.p[i] = yT[i];
        for (int i = 0; i <= l; ++i)     pd.p[i] = yC[i];
        k_combineln<1><<<TT / 4, 128>>>(pc, l + 2, theta + l * (NLl + 1),
                                        pd, l + 1, gma + l * NLl,
                                        cnw + l * Dd, cnb + l * Dd, p_tokin, p_chr);
        mamba(p_chr, BNb, Mm, l, 1, nullptr, p_chout, 0, 0);
        mamba(p_chr, BNb, Mm, l, 2, nullptr, p_chout, 1, 1);
        k_transback<<<4096, 256>>>(p_chout, p_tokin, yC[l + 1]);
    }

    k_ln<<<TT / 4, 128>>>(yC[4], n2w1, n2b1, p_tmp, TT);
    k_ln_n<<<(BMr * Dd + 255) / 256, 256>>>(p_tmp, n2w2, n2b2, p_norm);
    // head GEMM: M=512, N=96, K=8064, split-K=21 (each slice K=384)
    k_mma<96><<<dim3(2, 4, KSPLIT), 256>>>(p_norm, headw, p_headp, nullptr,
                                           Nn * Dd, 384, 0);
    k_headred<<<(Bb * PREDp * Mm + 255) / 256, 256>>>(p_headp, headb, p_mean, p_std,
                                                      (float*)d_out);
}

// round 5
// speedup vs baseline: 2.0358x; 1.0937x over previous
#include <cuda_runtime.h>
#include <cuda_bf16.h>
#include <math.h>
#include <stdint.h>

// ---- problem dims ----
#define Bb   16
#define Ll   512
#define Mm   32
#define PREDp 96
#define Pp   16
#define Sss  8
#define Dd   128
#define NSTn 16
#define DCc  4
#define NLl  4
#define Nn   63
#define DIi  256
#define DTRr 8
#define BMr  512
#define TT   32256        // = 512*63 = 1008*32 = 252*128
#define BNb  1008
#define KSPLIT 21         // head GEMM split-K slices (8064 = 21*384)

// ---- static device scratch ----
__device__ float g_y[9][(size_t)TT * Dd];
__device__ float g_xn[(size_t)BMr * Ll];
__device__ float g_mean[BMr];
__device__ float g_std[BMr];
__device__ float g_tokin[(size_t)TT * Dd];
__device__ float g_norm[(size_t)TT * Dd];
__device__ float g_chr[(size_t)TT * Dd];
__device__ float g_chout[(size_t)TT * Dd];
__device__ float g_xz[(size_t)TT * 1024];      // up to 2 roles x (xi|z)
__device__ float g_ys[(size_t)TT * 512];       // up to 2 roles x DI
__device__ float g_tmp[(size_t)TT * Dd];
__device__ float g_wpack[128 * 512];
__device__ float g_headp[(size_t)KSPLIT * BMr * PREDp];

// ======================= warp-mma bf16-split GEMM =======================
// C[M,NT] = A[M,K] @ Bw[NT,K]^T, fp32 in/out, bf16 hi/lo split (3 HMMA terms).
// grid = (ceil(NT/64), M/128, nsplit), block = 256 (8 warps of 32x32 tiles).
// flags: 1 = accumulate into C, 2 = add R. klen % 32 == 0.

#define SASTR 40   // smem row stride (bf16): 80B -> conflict-free ldmatrix

__device__ __forceinline__ uint32_t smem_u32(const void* p) {
    return (uint32_t)__cvta_generic_to_shared(p);
}

__device__ __forceinline__ void mma16816(float* d, const uint32_t* a, const uint32_t* b) {
    asm volatile(
        "mma.sync.aligned.m16n8k16.row.col.f32.bf16.bf16.f32 "
        "{%0,%1,%2,%3},{%4,%5,%6,%7},{%8,%9},{%0,%1,%2,%3};"
        : "+f"(d[0]), "+f"(d[1]), "+f"(d[2]), "+f"(d[3])
        : "r"(a[0]), "r"(a[1]), "r"(a[2]), "r"(a[3]), "r"(b[0]), "r"(b[1]));
}

__device__ __forceinline__ void ldm_x4(uint32_t* r, uint32_t a) {
    asm volatile("ldmatrix.sync.aligned.m8n8.x4.shared.b16 {%0,%1,%2,%3}, [%4];"
                 : "=r"(r[0]), "=r"(r[1]), "=r"(r[2]), "=r"(r[3]) : "r"(a));
}

union BH2 { __nv_bfloat16 h[2]; uint32_t u; };

template <int NT>
__global__ __launch_bounds__(256) void k_mma(const float* __restrict__ A,
                                             const float* __restrict__ Bw,
                                             float* __restrict__ C,
                                             const float* __restrict__ R,
                                             int K, int klen, int flags) {
    __shared__ __nv_bfloat16 sA[2][128 * SASTR];
    __shared__ __nv_bfloat16 sB[2][64 * SASTR];

    int tid = threadIdx.x;
    int warp = tid >> 5, lane = tid & 31;
    int gq = lane >> 2, tig = lane & 3;
    int warpM = warp >> 1, warpN = warp & 1;
    int m0 = blockIdx.y * 128;
    int n0 = blockIdx.x * 64;
    int kbeg = blockIdx.z * klen;
    C += (size_t)blockIdx.z * ((size_t)gridDim.y * 128) * NT;

    // ldmatrix per-thread source offsets (element units within smem tile)
    int g = lane >> 3, rr = lane & 7;
    int aoff = (warpM * 32 + (g & 1) * 8 + rr) * SASTR + (g >> 1) * 8;
    int boff = (warpN * 32 + (g >> 1) * 8 + rr) * SASTR + (g & 1) * 8;
    uint32_t sA0 = smem_u32(&sA[0][0]), sA1 = smem_u32(&sA[1][0]);
    uint32_t sB0 = smem_u32(&sB[0][0]), sB1 = smem_u32(&sB[1][0]);

    float acc[2][4][4];
#pragma unroll
    for (int i = 0; i < 2; ++i)
#pragma unroll
        for (int j = 0; j < 4; ++j)
#pragma unroll
            for (int r = 0; r < 4; ++r) acc[i][j][r] = 0.f;

    float4 ra[4], rb[2];

    auto ldA = [&](int k0) {
#pragma unroll
        for (int t = 0; t < 4; ++t) {
            int gg = tid + t * 256;
            int row = gg >> 3, c = (gg & 7) << 2;
            ra[t] = *reinterpret_cast<const float4*>(A + (size_t)(m0 + row) * K + k0 + c);
        }
    };
    auto ldB = [&](int k0) {
#pragma unroll
        for (int t = 0; t < 2; ++t) {
            int gg = tid + t * 256;
            int row = gg >> 3, c = (gg & 7) << 2;
            int grow = n0 + row;
            if ((NT & 63) == 0 || grow < NT)
                rb[t] = *reinterpret_cast<const float4*>(Bw + (size_t)grow * K + k0 + c);
            else
                rb[t] = make_float4(0.f, 0.f, 0.f, 0.f);
        }
    };

    ldA(kbeg); ldB(kbeg);
    int nch = klen >> 5;
    for (int ch = 0; ch < nch; ++ch) {
#pragma unroll
        for (int t = 0; t < 4; ++t) {
            int gg = tid + t * 256;
            int row = gg >> 3, c = (gg & 7) << 2;
            float v[4] = {ra[t].x, ra[t].y, ra[t].z, ra[t].w};
            BH2 h0, h1, l0, l1;
#pragma unroll
            for (int q = 0; q < 2; ++q) {
                h0.h[q] = __float2bfloat16(v[q]);
                l0.h[q] = __float2bfloat16(v[q] - __bfloat162float(h0.h[q]));
                h1.h[q] = __float2bfloat16(v[2 + q]);
                l1.h[q] = __float2bfloat16(v[2 + q] - __bfloat162float(h1.h[q]));
            }
            uint32_t* ph = reinterpret_cast<uint32_t*>(&sA[0][row * SASTR + c]);
            uint32_t* pl = reinterpret_cast<uint32_t*>(&sA[1][row * SASTR + c]);
            ph[0] = h0.u; ph[1] = h1.u; pl[0] = l0.u; pl[1] = l1.u;
        }
#pragma unroll
        for (int t = 0; t < 2; ++t) {
            int gg = tid + t * 256;
            int row = gg >> 3, c = (gg & 7) << 2;
            float v[4] = {rb[t].x, rb[t].y, rb[t].z, rb[t].w};
            BH2 h0, h1, l0, l1;
#pragma unroll
            for (int q = 0; q < 2; ++q) {
                h0.h[q] = __float2bfloat16(v[q]);
                l0.h[q] = __float2bfloat16(v[q] - __bfloat162float(h0.h[q]));
                h1.h[q] = __float2bfloat16(v[2 + q]);
                l1.h[q] = __float2bfloat16(v[2 + q] - __bfloat162float(h1.h[q]));
            }
            uint32_t* ph = reinterpret_cast<uint32_t*>(&sB[0][row * SASTR + c]);
            uint32_t* pl = reinterpret_cast<uint32_t*>(&sB[1][row * SASTR + c]);
            ph[0] = h0.u; ph[1] = h1.u; pl[0] = l0.u; pl[1] = l1.u;
        }
        __syncthreads();
        if (ch + 1 < nch) { ldA(kbeg + ((ch + 1) << 5)); ldB(kbeg + ((ch + 1) << 5)); }

#pragma unroll
        for (int kk = 0; kk < 2; ++kk) {
            int kb = kk * 16;
            uint32_t ah[2][4], al[2][4];
            ldm_x4(ah[0], sA0 + (uint32_t)(aoff + kb) * 2);
            ldm_x4(ah[1], sA0 + (uint32_t)(aoff + 16 * SASTR + kb) * 2);
            ldm_x4(al[0], sA1 + (uint32_t)(aoff + kb) * 2);
            ldm_x4(al[1], sA1 + (uint32_t)(aoff + 16 * SASTR + kb) * 2);
            uint32_t bh[4][2], bl[4][2], t0[4], t1[4];
            ldm_x4(t0, sB0 + (uint32_t)(boff + kb) * 2);
            ldm_x4(t1, sB0 + (uint32_t)(boff + 16 * SASTR + kb) * 2);
            bh[0][0] = t0[0]; bh[0][1] = t0[1]; bh[1][0] = t0[2]; bh[1][1] = t0[3];
            bh[2][0] = t1[0]; bh[2][1] = t1[1]; bh[3][0] = t1[2]; bh[3][1] = t1[3];
            ldm_x4(t0, sB1 + (uint32_t)(boff + kb) * 2);
            ldm_x4(t1, sB1 + (uint32_t)(boff + 16 * SASTR + kb) * 2);
            bl[0][0] = t0[0]; bl[0][1] = t0[1]; bl[1][0] = t0[2]; bl[1][1] = t0[3];
            bl[2][0] = t1[0]; bl[2][1] = t1[1]; bl[3][0] = t1[2]; bl[3][1] = t1[3];
#pragma unroll
            for (int i = 0; i < 2; ++i)
#pragma unroll
                for (int j = 0; j < 4; ++j) {
                    mma16816(acc[i][j], ah[i], bh[j]);
                    mma16816(acc[i][j], ah[i], bl[j]);
                    mma16816(acc[i][j], al[i], bh[j]);
                }
        }
        __syncthreads();
    }

#pragma unroll
    for (int i = 0; i < 2; ++i) {
        int grow = m0 + warpM * 32 + i * 16 + gq;
#pragma unroll
        for (int j = 0; j < 4; ++j) {
            int gcol = n0 + warpN * 32 + j * 8 + 2 * tig;
            if ((NT & 63) != 0 && gcol >= NT) continue;
            size_t o0 = (size_t)grow * NT + gcol;
            size_t o1 = (size_t)(grow + 8) * NT + gcol;
            float2 v0 = make_float2(acc[i][j][0], acc[i][j][1]);
            float2 v1 = make_float2(acc[i][j][2], acc[i][j][3]);
            if (flags & 2) {
                float2 t0 = *reinterpret_cast<const float2*>(R + o0);
                float2 t1 = *reinterpret_cast<const float2*>(R + o1);
                v0.x += t0.x; v0.y += t0.y; v1.x += t1.x; v1.y += t1.y;
            }
            if (flags & 1) {
                float2 t0 = *reinterpret_cast<const float2*>(C + o0);
                float2 t1 = *reinterpret_cast<const float2*>(C + o1);
                v0.x += t0.x; v0.y += t0.y; v1.x += t1.x; v1.y += t1.y;
            }
            *reinterpret_cast<float2*>(C + o0) = v0;
            *reinterpret_cast<float2*>(C + o1) = v1;
        }
    }
}

// ======================= fused conv+x_proj+dt+scan (multi-role) =======================
// grid = (batch, nroles). role r: xz cols [r*512, r*512+512), y cols [r*256..),
// weights offset by r role-slots, rev = r (role 1 = backward scan).
__global__ __launch_bounds__(256) void k_fscan(
    const float* __restrict__ xz, int xzs,
    const float* __restrict__ xw, const float* __restrict__ dtw,
    const float* __restrict__ dtb, const float* __restrict__ cw,
    const float* __restrict__ cb, const float* __restrict__ alog,
    const float* __restrict__ dssm, float* __restrict__ y, int ystr, int slen) {
    __shared__ float sW[40 * DIi];
    __shared__ float su[DIi];
    __shared__ float sx[40];

    int r = blockIdx.y;
    int rev = r;
    xz  += (size_t)r * 512;
    xw  += (size_t)r * 40 * DIi;
    dtw += (size_t)r * DIi * DTRr;
    dtb += (size_t)r * DIi;
    cw  += (size_t)r * DIi * DCc;
    cb  += (size_t)r * DIi;
    alog += (size_t)r * DIi * NSTn;
    dssm += (size_t)r * DIi;
    y   += (size_t)r * 256;

    int c = threadIdx.x;
    int warp = c >> 5, lane = c & 31;
    int b = blockIdx.x;

    for (int i = c; i < 40 * DIi; i += 256) sW[i] = xw[i];

    float dtwr[DTRr];
#pragma unroll
    for (int q = 0; q < DTRr; ++q) dtwr[q] = dtw[c * DTRr + q];
    float dtbr = dtb[c];
    float cw0 = cw[c * 4 + 0], cw1 = cw[c * 4 + 1], cw2 = cw[c * 4 + 2], cw3 = cw[c * 4 + 3];
    float cbr = cb[c];
    float dss = dssm[c];

    float a[NSTn];
#pragma unroll
    for (int n = 0; n < NSTn; ++n) a[n] = -__expf(alog[c * NSTn + n]);
    float a0 = a[0];
    bool geom = true;
#pragma unroll
    for (int n = 1; n < NSTn; ++n)
        geom = geom && (fabsf(a[n] - (float)(n + 1) * a0) <= 1e-4f * fabsf(a[n]));
    float h[NSTn];
#pragma unroll
    for (int n = 0; n < NSTn; ++n) h[n] = 0.f;

    __syncthreads();

    size_t base = (size_t)b * slen;
    int s0 = rev ? slen - 1 : 0;
    float xi_nx = xz[(base + s0) * xzs + c];
    float z_nx  = xz[(base + s0) * xzs + DIi + c];
    float r0 = 0.f, r1 = 0.f, r2 = 0.f, r3 = 0.f;   // register conv ring

    for (int step = 0; step < slen; ++step) {
        int s = rev ? slen - 1 - step : step;
        r0 = r1; r1 = r2; r2 = r3; r3 = xi_nx;
        float zv = z_nx;
        if (step + 1 < slen) {
            int sn = rev ? s - 1 : s + 1;
            xi_nx = xz[(base + sn) * xzs + c];
            z_nx  = xz[(base + sn) * xzs + DIi + c];
        }
        // depthwise conv (oldest tap gets cw0) + SiLU — no cross-channel data
        float acc = fmaf(cw0, r0, fmaf(cw1, r1, fmaf(cw2, r2, fmaf(cw3, r3, cbr))));
        float uv = acc / (1.f + __expf(-acc));
        su[c] = uv;
        __syncthreads();
        // x_proj matvec: 8 warps x 5 outputs
#pragma unroll
        for (int oo = 0; oo < 5; ++oo) {
            int o = warp * 5 + oo;
            const float* wr = &sW[o * DIi];
            float p = 0.f;
#pragma unroll
            for (int k8 = 0; k8 < 8; ++k8)
                p = fmaf(su[lane + 32 * k8], wr[lane + 32 * k8], p);
#pragma unroll
            for (int off = 16; off; off >>= 1) p += __shfl_xor_sync(0xffffffffu, p, off);
            if (lane == 0) sx[o] = p;
        }
        __syncthreads();
        float dtacc = dtbr;
#pragma unroll
        for (int q = 0; q < DTRr; ++q) dtacc = fmaf(sx[q], dtwr[q], dtacc);
        float dtv = (dtacc > 20.f) ? dtacc : log1pf(__expf(dtacc));
        float du = dtv * uv;
        float ysum = 0.f;
        if (geom) {
            float w = __expf(dtv * a0);
            float e = 1.f;
#pragma unroll
            for (int n = 0; n < NSTn; ++n) {
                e *= w;
                h[n] = fmaf(h[n], e, du * sx[8 + n]);
                ysum = fmaf(h[n], sx[24 + n], ysum);
            }
        } else {
#pragma unroll
            for (int n = 0; n < NSTn; ++n) {
                float e = __expf(dtv * a[n]);
                h[n] = fmaf(h[n], e, du * sx[8 + n]);
                ysum = fmaf(h[n], sx[24 + n], ysum);
            }
        }
        float sg = 1.f / (1.f + __expf(-zv));
        y[(base + s) * ystr + c] = (ysum + uv * dss) * (zv * sg);
    }
}

// ======================= fused combine + LN (+transpose) =======================
struct P5 { const float* p[5]; };

template <int TRANS>
__global__ void k_combineln(P5 pa, int na, const float* __restrict__ ra,
                            P5 pb, int nb, const float* __restrict__ rb,
                            const float* __restrict__ w, const float* __restrict__ bia,
                            float* __restrict__ comb, float* __restrict__ normout) {
    __shared__ float ca[5], cb2[5];
    if (threadIdx.x == 0) {
        float mx = -1e30f;
        for (int i = 0; i < na; ++i) mx = fmaxf(mx, ra[i]);
        float s = 0.f;
        for (int i = 0; i < na; ++i) { ca[i] = __expf(ra[i] - mx); s += ca[i]; }
        for (int i = 0; i < na; ++i) ca[i] /= s;
        mx = -1e30f;
        for (int i = 0; i < nb; ++i) mx = fmaxf(mx, rb[i]);
        s = 0.f;
        for (int i = 0; i < nb; ++i) { cb2[i] = __expf(rb[i] - mx); s += cb2[i]; }
        for (int i = 0; i < nb; ++i) cb2[i] /= s;
    }
    __syncthreads();
    int warp = threadIdx.x >> 5, lane = threadIdx.x & 31;
    int row = blockIdx.x * 4 + warp;
    if (row >= TT) return;
    int irow = row;
    if (TRANS) {
        int m = row & 31;
        int bn = row >> 5;
        int n = bn % Nn, b = bn / Nn;
        irow = (b * Mm + m) * Nn + n;
    }
    float v[4];
#pragma unroll
    for (int q = 0; q < 4; ++q) {
        size_t off = (size_t)irow * Dd + lane + 32 * q;
        float acc = 0.f;
        for (int j = 0; j < na; ++j) acc = fmaf(ca[j], pa.p[j][off], acc);
        for (int j = 0; j < nb; ++j) acc = fmaf(cb2[j], pb.p[j][off], acc);
        v[q] = acc;
        comb[off] = acc;
    }
    float s = v[0] + v[1] + v[2] + v[3];
#pragma unroll
    for (int o = 16; o; o >>= 1) s += __shfl_xor_sync(0xffffffffu, s, o);
    float mu = s * (1.f / Dd);
    float q0 = 0.f;
#pragma unroll
    for (int q = 0; q < 4; ++q) { v[q] -= mu; q0 += v[q] * v[q]; }
#pragma unroll
    for (int o = 16; o; o >>= 1) q0 += __shfl_xor_sync(0xffffffffu, q0, o);
    float r = rsqrtf(q0 * (1.f / Dd) + 1e-5f);
    float* orow = normout + (size_t)row * Dd;
#pragma unroll
    for (int q = 0; q < 4; ++q) {
        int e = lane + 32 * q;
        orow[e] = v[q] * r * w[e] + bia[e];
    }
}

// ======================= other supporting kernels =======================

__global__ void k_stats(const float* __restrict__ x, float* __restrict__ mean,
                        float* __restrict__ stdv, float* __restrict__ xn) {
    int bm = blockIdx.x;
    int b = bm >> 5, m = bm & 31;
    int tid = threadIdx.x;
    float s = 0.f, sq = 0.f;
    for (int l = tid; l < Ll; l += 256) {
        float v = x[((size_t)b * Ll + l) * Mm + m];
        s += v; sq += v * v;
    }
    __shared__ float sh1[256], sh2[256];
    sh1[tid] = s; sh2[tid] = sq;
    __syncthreads();
    for (int o = 128; o; o >>= 1) {
        if (tid < o) { sh1[tid] += sh1[tid + o]; sh2[tid] += sh2[tid + o]; }
        __syncthreads();
    }
    __shared__ float smu, ssd;
    if (tid == 0) {
        float mu = sh1[0] / (float)Ll;
        float var = (sh2[0] - (float)Ll * mu * mu) / (float)(Ll - 1);
        if (var < 0.f) var = 0.f;
        float sd = sqrtf(var) + 1e-5f;
        smu = mu; ssd = sd;
        mean[bm] = mu; stdv[bm] = sd;
    }
    __syncthreads();
    float inv = 1.f / ssd;
    float mu = smu;
    for (int l = tid; l < Ll; l += 256) {
        xn[(size_t)bm * Ll + l] = (x[((size_t)b * Ll + l) * Mm + m] - mu) * inv;
    }
}

__global__ void k_patch(const float* __restrict__ xn, const float* __restrict__ pw,
                        const float* __restrict__ pb, const float* __restrict__ pos,
                        float* __restrict__ h) {
    int blk = blockIdx.x;
    int n = blk % Nn, bm = blk / Nn;
    int d = threadIdx.x;
    __shared__ float xs[Pp];
    if (d < Pp) xs[d] = xn[(size_t)bm * Ll + n * Sss + d];
    __syncthreads();
    float acc = pb[d];
#pragma unroll
    for (int p = 0; p < Pp; ++p) acc = fmaf(xs[p], pw[d * Pp + p], acc);
    acc += pos[n * Dd + d];
    h[(size_t)blk * Dd + d] = acc;
}

__global__ void k_ln(const float* __restrict__ x, const float* __restrict__ w,
                     const float* __restrict__ bia, float* __restrict__ out, int rows) {
    int warp = threadIdx.x >> 5, lane = threadIdx.x & 31;
    int row = blockIdx.x * 4 + warp;
    if (row >= rows) return;
    const float* xr = x + (size_t)row * Dd;
    float v0 = xr[lane], v1 = xr[lane + 32], v2 = xr[lane + 64], v3 = xr[lane + 96];
    float s = v0 + v1 + v2 + v3;
#pragma unroll
    for (int o = 16; o; o >>= 1) s += __shfl_xor_sync(0xffffffffu, s, o);
    float mu = s * (1.f / Dd);
    float d0 = v0 - mu, d1 = v1 - mu, d2 = v2 - mu, d3 = v3 - mu;
    float q = d0 * d0 + d1 * d1 + d2 * d2 + d3 * d3;
#pragma unroll
    for (int o = 16; o; o >>= 1) q += __shfl_xor_sync(0xffffffffu, q, o);
    float r = rsqrtf(q * (1.f / Dd) + 1e-5f);
    float* orow = out + (size_t)row * Dd;
    orow[lane]      = d0 * r * w[lane]      + bia[lane];
    orow[lane + 32] = d1 * r * w[lane + 32] + bia[lane + 32];
    orow[lane + 64] = d2 * r * w[lane + 64] + bia[lane + 64];
    orow[lane + 96] = d3 * r * w[lane + 96] + bia[lane + 96];
}

__global__ void k_transback(const float* __restrict__ chout, const float* __restrict__ chin,
                            float* __restrict__ out) {
    size_t total = (size_t)TT * Dd;
    for (size_t i = (size_t)blockIdx.x * blockDim.x + threadIdx.x; i < total;
         i += (size_t)gridDim.x * blockDim.x) {
        int d = (int)(i & 127);
        size_t rest = i >> 7;
        int n = (int)(rest % Nn);
        int bm = (int)(rest / Nn);
        int m = bm & 31, b = bm >> 5;
        size_t src = (((size_t)(b * Nn + n) * Mm + m) << 7) + d;
        out[i] = chout[src] + chin[i];
    }
}

__global__ void k_ln_n(const float* __restrict__ x, const float* __restrict__ w2,
                       const float* __restrict__ b2, float* __restrict__ out) {
    int idx = blockIdx.x * 256 + threadIdx.x;
    if (idx >= BMr * Dd) return;
    int d = idx & 127, bm = idx >> 7;
    const float* base = x + (size_t)bm * Nn * Dd + d;
    float s = 0.f, q = 0.f;
    for (int n = 0; n < Nn; ++n) { float v = base[(size_t)n * Dd]; s += v; q += v * v; }
    float mu = s * (1.f / Nn);
    float var = q * (1.f / Nn) - mu * mu;
    if (var < 0.f) var = 0.f;
    float r = rsqrtf(var + 1e-5f);
    float* ob = out + (size_t)bm * Nn * Dd + d;
    for (int n = 0; n < Nn; ++n)
        ob[(size_t)n * Dd] = (base[(size_t)n * Dd] - mu) * r * w2[n] + b2[n];
}

// repack channel out_proj weights: wp[d][0:256) = w1[d], wp[d][256:512) = w2[d]
__global__ void k_repack(const float* __restrict__ w1, const float* __restrict__ w2,
                         float* __restrict__ wp) {
    int i = blockIdx.x * 256 + threadIdx.x;
    if (i >= 128 * 256) return;
    int d = i >> 8, k = i & 255;
    wp[d * 512 + k] = w1[i];
    wp[d * 512 + 256 + k] = w2[i];
}

__global__ void k_headred(const float* __restrict__ hp, const float* __restrict__ hb,
                          const float* __restrict__ mean, const float* __restrict__ stdv,
                          float* __restrict__ out) {
    int idx = blockIdx.x * 256 + threadIdx.x;
    if (idx >= Bb * PREDp * Mm) return;
    int m = idx % Mm;
    int p = (idx / Mm) % PREDp;
    int b = idx / (Mm * PREDp);
    int bm = b * Mm + m;
    float s = 0.f;
#pragma unroll 3
    for (int z = 0; z < KSPLIT; ++z)
        s += hp[(size_t)z * BMr * PREDp + (size_t)bm * PREDp + p];
    out[idx] = (s + hb[p]) * stdv[bm] + mean[bm];
}

// ======================= host orchestration =======================

extern "C" void kernel_launch(void* const* d_in, const int* in_sizes, int n_in,
                              void* d_out, int out_size) {
    (void)in_sizes; (void)n_in; (void)out_size;
    const float* x      = (const float*)d_in[0];
    const float* patchw = (const float*)d_in[1];
    const float* patchb = (const float*)d_in[2];
    const float* pos    = (const float*)d_in[3];
    const float* alpha  = (const float*)d_in[4];
    const float* beta   = (const float*)d_in[5];
    const float* theta  = (const float*)d_in[6];
    const float* gma    = (const float*)d_in[7];
    const float* tnw    = (const float*)d_in[8];
    const float* tnb    = (const float*)d_in[9];
    const float* cnw    = (const float*)d_in[10];
    const float* cnb    = (const float*)d_in[11];
    const float* inw    = (const float*)d_in[12];
    const float* cvw    = (const float*)d_in[13];
    const float* cvb    = (const float*)d_in[14];
    const float* xpw    = (const float*)d_in[15];
    const float* dtw    = (const float*)d_in[16];
    const float* dtbv   = (const float*)d_in[17];
    const float* alog   = (const float*)d_in[18];
    const float* dssm   = (const float*)d_in[19];
    const float* outw   = (const float*)d_in[20];
    const float* n2w1   = (const float*)d_in[21];
    const float* n2b1   = (const float*)d_in[22];
    const float* n2w2   = (const float*)d_in[23];
    const float* n2b2   = (const float*)d_in[24];
    const float* headw  = (const float*)d_in[25];
    const float* headb  = (const float*)d_in[26];

    float *p_y, *p_xn, *p_mean, *p_std, *p_tokin, *p_norm, *p_chr, *p_chout;
    float *p_xz, *p_ys, *p_tmp, *p_headp, *p_wpack;
    cudaGetSymbolAddress((void**)&p_y,     g_y);
    cudaGetSymbolAddress((void**)&p_xn,    g_xn);
    cudaGetSymbolAddress((void**)&p_mean,  g_mean);
    cudaGetSymbolAddress((void**)&p_std,   g_std);
    cudaGetSymbolAddress((void**)&p_tokin, g_tokin);
    cudaGetSymbolAddress((void**)&p_norm,  g_norm);
    cudaGetSymbolAddress((void**)&p_chr,   g_chr);
    cudaGetSymbolAddress((void**)&p_chout, g_chout);
    cudaGetSymbolAddress((void**)&p_xz,    g_xz);
    cudaGetSymbolAddress((void**)&p_ys,    g_ys);
    cudaGetSymbolAddress((void**)&p_tmp,   g_tmp);
    cudaGetSymbolAddress((void**)&p_headp, g_headp);
    cudaGetSymbolAddress((void**)&p_wpack, g_wpack);

    float* yT[5]; float* yC[5];
    yT[0] = p_y; yC[0] = p_y;
    for (int i = 1; i <= 4; ++i) {
        yT[i] = p_y + (size_t)i * TT * Dd;
        yC[i] = p_y + (size_t)(4 + i) * TT * Dd;
    }

    k_stats<<<BMr, 256>>>(x, p_mean, p_std, p_xn);
    k_patch<<<TT, Dd>>>(p_xn, patchw, patchb, pos, p_y);

    const int GY = TT / 128;   // 252

    for (int l = 0; l < NLl; ++l) {
        // ---- token mixing ----
        P5 pa = {}, pb = {};
        for (int i = 0; i <= l; ++i) { pa.p[i] = yT[i]; pb.p[i] = yC[i]; }
        k_combineln<0><<<TT / 4, 128>>>(pa, l + 1, alpha + l * NLl,
                                        pb, l + 1, beta + l * NLl,
                                        tnw + l * Dd, tnb + l * Dd, p_tokin, p_norm);
        {
            size_t lr = (size_t)(l * 3 + 0);
            k_mma<512><<<dim3(8, GY, 1), 256>>>(p_norm, inw + lr * 2 * DIi * Dd, p_xz,
                                                nullptr, Dd, Dd, 0);
            k_fscan<<<dim3(BMr, 1), 256>>>(p_xz, 512,
                                           xpw + lr * 40 * DIi, dtw + lr * DIi * DTRr,
                                           dtbv + lr * DIi, cvw + lr * DIi * DCc,
                                           cvb + lr * DIi, alog + lr * DIi * NSTn,
                                           dssm + lr * DIi, p_ys, 256, Nn);
            k_mma<128><<<dim3(2, GY, 1), 256>>>(p_ys, outw + lr * Dd * DIi, yT[l + 1],
                                                p_tokin, DIi, DIi, 2);
        }

        // ---- channel mixing (fwd+bwd fused) ----
        P5 pc = {}, pd = {};
        for (int i = 0; i <= l + 1; ++i) pc.p[i] = yT[i];
        for (int i = 0; i <= l; ++i)     pd.p[i] = yC[i];
        k_combineln<1><<<TT / 4, 128>>>(pc, l + 2, theta + l * (NLl + 1),
                                        pd, l + 1, gma + l * NLl,
                                        cnw + l * Dd, cnb + l * Dd, p_tokin, p_chr);
        {
            size_t lr = (size_t)(l * 3 + 1);       // role 1; role 2 contiguous after
            k_repack<<<128, 256>>>(outw + lr * Dd * DIi, outw + (lr + 1) * Dd * DIi, p_wpack);
            k_mma<1024><<<dim3(16, GY, 1), 256>>>(p_chr, inw + lr * 2 * DIi * Dd, p_xz,
                                                  nullptr, Dd, Dd, 0);
            k_fscan<<<dim3(BNb, 2), 256>>>(p_xz, 1024,
                                           xpw + lr * 40 * DIi, dtw + lr * DIi * DTRr,
                                           dtbv + lr * DIi, cvw + lr * DIi * DCc,
                                           cvb + lr * DIi, alog + lr * DIi * NSTn,
                                           dssm + lr * DIi, p_ys, 512, Mm);
            k_mma<128><<<dim3(2, GY, 1), 256>>>(p_ys, p_wpack, p_chout,
                                                nullptr, 512, 512, 0);
        }
        k_transback<<<4096, 256>>>(p_chout, p_tokin, yC[l + 1]);
    }

    k_ln<<<TT / 4, 128>>>(yC[4], n2w1, n2b1, p_tmp, TT);
    k_ln_n<<<(BMr * Dd + 255) / 256, 256>>>(p_tmp, n2w2, n2b2, p_norm);
    k_mma<96><<<dim3(2, 4, KSPLIT), 256>>>(p_norm, headw, p_headp, nullptr,
                                           Nn * Dd, 384, 0);
    k_headred<<<(Bb * PREDp * Mm + 255) / 256, 256>>>(p_headp, headb, p_mean, p_std,
                                                      (float*)d_out);
}